// round 6
// baseline (speedup 1.0000x reference)
#include <cuda_runtime.h>
#include <math.h>

#define D_MODEL 1024
#define N_HEADS 16
#define HEAD_DIM 64
#define SEQ 2048
#define MAXB 2

// Scratch (no allocations allowed)
__device__ float g_q[MAXB * N_HEADS * SEQ * HEAD_DIM];
__device__ float g_k[MAXB * N_HEADS * SEQ * HEAD_DIM];
__device__ float g_v[MAXB * N_HEADS * SEQ * HEAD_DIM];
__device__ float g_attn[MAXB * SEQ * D_MODEL];

// ---------------------------------------------------------------------------
// GEMM: C = A (MxK) * W^T, W stored [N,K] row-major (torch Linear weights).
// K = N = D_MODEL = 1024. BM=BN=128, BK=16, 256 threads, 8x8 per thread.
// MODE 0: C row-major [M, D_MODEL]
// MODE 1: C written as [B, H, S, HD] (for Q/K/V)
// ---------------------------------------------------------------------------
template <int MODE>
__global__ void __launch_bounds__(256) gemm_nt(const float* __restrict__ A,
                                               const float* __restrict__ W,
                                               float* __restrict__ C, int S) {
    const int BM = 128, BN = 128, BK = 16, PAD = 4;
    __shared__ float As[BK][BM + PAD];
    __shared__ float Bs[BK][BN + PAD];

    int tid = threadIdx.x;
    int tx = tid & 15;        // 0..15 -> N groups of 8
    int ty = tid >> 4;        // 0..15 -> M groups of 8
    int mBase = blockIdx.x * BM;
    int nBase = blockIdx.y * BN;

    float acc[8][8];
#pragma unroll
    for (int i = 0; i < 8; ++i)
#pragma unroll
        for (int j = 0; j < 8; ++j) acc[i][j] = 0.0f;

    for (int k0 = 0; k0 < D_MODEL; k0 += BK) {
#pragma unroll
        for (int it = 0; it < 8; ++it) {
            int e = it * 256 + tid;
            int m = e >> 4, kk = e & 15;
            As[kk][m] = A[(mBase + m) * D_MODEL + k0 + kk];
        }
#pragma unroll
        for (int it = 0; it < 8; ++it) {
            int e = it * 256 + tid;
            int n = e >> 4, kk = e & 15;
            Bs[kk][n] = W[(nBase + n) * D_MODEL + k0 + kk];
        }
        __syncthreads();

#pragma unroll
        for (int kk = 0; kk < BK; ++kk) {
            float a[8], b[8];
            float4 a0 = *(const float4*)&As[kk][ty * 8];
            float4 a1 = *(const float4*)&As[kk][ty * 8 + 4];
            float4 b0 = *(const float4*)&Bs[kk][tx * 8];
            float4 b1 = *(const float4*)&Bs[kk][tx * 8 + 4];
            a[0] = a0.x; a[1] = a0.y; a[2] = a0.z; a[3] = a0.w;
            a[4] = a1.x; a[5] = a1.y; a[6] = a1.z; a[7] = a1.w;
            b[0] = b0.x; b[1] = b0.y; b[2] = b0.z; b[3] = b0.w;
            b[4] = b1.x; b[5] = b1.y; b[6] = b1.z; b[7] = b1.w;
#pragma unroll
            for (int i = 0; i < 8; ++i)
#pragma unroll
                for (int j = 0; j < 8; ++j) acc[i][j] += a[i] * b[j];
        }
        __syncthreads();
    }

#pragma unroll
    for (int i = 0; i < 8; ++i) {
        int t = mBase + ty * 8 + i;
#pragma unroll
        for (int j = 0; j < 8; ++j) {
            int col = nBase + tx * 8 + j;
            if (MODE == 0) {
                C[(size_t)t * D_MODEL + col] = acc[i][j];
            } else {
                int b = t / S, s = t - b * S;
                int h = col >> 6, hd = col & 63;
                C[(((size_t)b * N_HEADS + h) * S + s) * HEAD_DIM + hd] = acc[i][j];
            }
        }
    }
}

// ---------------------------------------------------------------------------
// RoPE on Q and K in-place. Layout [BH, S, HD]. One thread per (bh, s, pair).
// ---------------------------------------------------------------------------
__global__ void rope_kernel(float* __restrict__ q, float* __restrict__ k,
                            int BH, int S) {
    int idx = blockIdx.x * blockDim.x + threadIdx.x;
    int total = BH * S * 32;
    if (idx >= total) return;
    int j = idx & 31;
    int s = (idx >> 5) % S;
    int bh = idx / (32 * S);

    float inv = powf(10000.0f, -(float)j / 32.0f);
    float ang = (float)s * inv;
    float sn, cs;
    sincosf(ang, &sn, &cs);

    size_t base = ((size_t)bh * S + s) * HEAD_DIM;
    float q1 = q[base + j], q2 = q[base + j + 32];
    q[base + j]      = q1 * cs - q2 * sn;
    q[base + j + 32] = q2 * cs + q1 * sn;
    float k1 = k[base + j], k2 = k[base + j + 32];
    k[base + j]      = k1 * cs - k2 * sn;
    k[base + j + 32] = k2 * cs + k1 * sn;
}

// ---------------------------------------------------------------------------
// Flash attention, causal, fp32. 64 queries per block, key tiles of 64.
// smem operands stored "k-index major" so GEMM fragment reads are contiguous
// float4 (pad 68 keeps alignment + kills bank conflicts).
// Grid: (S/64, B*H), 256 threads.
// ---------------------------------------------------------------------------
__global__ void __launch_bounds__(256) flash_kernel(const float* __restrict__ Q,
                                                    const float* __restrict__ K,
                                                    const float* __restrict__ V,
                                                    float* __restrict__ O, int S) {
    const int P = 68;
    extern __shared__ float sm[];
    float* Qt = sm;                  // [64][68]  Qt[d][i]
    float* Kt = Qt + 64 * P;         // [64][68]  Kt[d][j]
    float* Vs = Kt + 64 * P;         // [64][68]  Vs[j][d]
    float* Pt = Vs + 64 * P;         // [64][68]  Pt[j][i]

    int tid = threadIdx.x;
    int tx = tid & 15;   // score col group / O col group
    int ty = tid >> 4;   // row group

    int qb = blockIdx.x * 64;
    int bh = blockIdx.y;
    const float* Qbase = Q + (size_t)bh * S * HEAD_DIM;
    const float* Kbase = K + (size_t)bh * S * HEAD_DIM;
    const float* Vbase = V + (size_t)bh * S * HEAD_DIM;

    // Load Q tile (scaled by 1/sqrt(HD))
#pragma unroll
    for (int it = 0; it < 16; ++it) {
        int e = it * 256 + tid;
        int i = e >> 6, d = e & 63;
        Qt[d * P + i] = Qbase[(size_t)(qb + i) * HEAD_DIM + d] * 0.125f;
    }

    float m_i[4], l_i[4], acc[4][4];
#pragma unroll
    for (int i = 0; i < 4; ++i) {
        m_i[i] = -1e30f;
        l_i[i] = 0.0f;
#pragma unroll
        for (int j = 0; j < 4; ++j) acc[i][j] = 0.0f;
    }

    int nkb = qb / 64 + 1;
    for (int kb = 0; kb < nkb; ++kb) {
        __syncthreads();  // prior PV phase done before overwriting tiles
#pragma unroll
        for (int it = 0; it < 16; ++it) {
            int e = it * 256 + tid;
            int j = e >> 6, d = e & 63;
            size_t g = (size_t)(kb * 64 + j) * HEAD_DIM + d;
            Kt[d * P + j] = Kbase[g];
            Vs[j * P + d] = Vbase[g];
        }
        __syncthreads();

        // ---- scores S = Qs * K^T ----
        float s[4][4];
#pragma unroll
        for (int i = 0; i < 4; ++i)
#pragma unroll
            for (int j = 0; j < 4; ++j) s[i][j] = 0.0f;

#pragma unroll 8
        for (int kk = 0; kk < 64; ++kk) {
            float4 av = *(const float4*)&Qt[kk * P + ty * 4];
            float4 bv = *(const float4*)&Kt[kk * P + tx * 4];
            float a[4] = {av.x, av.y, av.z, av.w};
            float b[4] = {bv.x, bv.y, bv.z, bv.w};
#pragma unroll
            for (int i = 0; i < 4; ++i)
#pragma unroll
                for (int j = 0; j < 4; ++j) s[i][j] += a[i] * b[j];
        }

        // ---- causal mask (only diagonal block needs it) ----
        if (kb == qb / 64) {
#pragma unroll
            for (int i = 0; i < 4; ++i)
#pragma unroll
                for (int j = 0; j < 4; ++j)
                    if (kb * 64 + tx * 4 + j > qb + ty * 4 + i) s[i][j] = -1e30f;
        }

        // ---- online softmax ----
        float al[4];
#pragma unroll
        for (int i = 0; i < 4; ++i) {
            float mm = fmaxf(fmaxf(s[i][0], s[i][1]), fmaxf(s[i][2], s[i][3]));
#pragma unroll
            for (int off = 8; off > 0; off >>= 1)
                mm = fmaxf(mm, __shfl_xor_sync(0xffffffffu, mm, off));
            float mn = fmaxf(m_i[i], mm);
            al[i] = __expf(m_i[i] - mn);
            m_i[i] = mn;
            float sum = 0.0f;
#pragma unroll
            for (int j = 0; j < 4; ++j) {
                float p = __expf(s[i][j] - mn);
                Pt[(tx * 4 + j) * P + ty * 4 + i] = p;
                sum += p;
            }
#pragma unroll
            for (int off = 8; off > 0; off >>= 1)
                sum += __shfl_xor_sync(0xffffffffu, sum, off);
            l_i[i] = l_i[i] * al[i] + sum;
        }
        __syncthreads();

        // ---- O = O*alpha + P * V ----
#pragma unroll
        for (int i = 0; i < 4; ++i)
#pragma unroll
            for (int j = 0; j < 4; ++j) acc[i][j] *= al[i];

#pragma unroll 8
        for (int kk = 0; kk < 64; ++kk) {
            float4 av = *(const float4*)&Pt[kk * P + ty * 4];
            float4 bv = *(const float4*)&Vs[kk * P + tx * 4];
            float a[4] = {av.x, av.y, av.z, av.w};
            float b[4] = {bv.x, bv.y, bv.z, bv.w};
#pragma unroll
            for (int i = 0; i < 4; ++i)
#pragma unroll
                for (int j = 0; j < 4; ++j) acc[i][j] += a[i] * b[j];
        }
    }

    // write out: [B, S, H*HD] so final projection sees contiguous [T, D]
    int b = bh / N_HEADS, h = bh % N_HEADS;
#pragma unroll
    for (int i = 0; i < 4; ++i) {
        int t = qb + ty * 4 + i;
        float inv_l = 1.0f / l_i[i];
#pragma unroll
        for (int j = 0; j < 4; ++j) {
            O[((size_t)b * S + t) * D_MODEL + h * HEAD_DIM + tx * 4 + j] =
                acc[i][j] * inv_l;
        }
    }
}

// ---------------------------------------------------------------------------
extern "C" void kernel_launch(void* const* d_in, const int* in_sizes, int n_in,
                              void* d_out, int out_size) {
    const float* x  = (const float*)d_in[0];
    const float* Wq = (const float*)d_in[1];
    const float* Wk = (const float*)d_in[2];
    const float* Wv = (const float*)d_in[3];
    const float* Wo = (const float*)d_in[4];

    int B = in_sizes[0] / (SEQ * D_MODEL);
    if (B < 1) B = 1;
    if (B > MAXB) B = MAXB;
    int T = B * SEQ;
    int BH = B * N_HEADS;

    float *q, *k, *v, *attn;
    cudaGetSymbolAddress((void**)&q, g_q);
    cudaGetSymbolAddress((void**)&k, g_k);
    cudaGetSymbolAddress((void**)&v, g_v);
    cudaGetSymbolAddress((void**)&attn, g_attn);

    dim3 gg(T / 128, D_MODEL / 128);
    gemm_nt<1><<<gg, 256>>>(x, Wq, q, SEQ);
    gemm_nt<1><<<gg, 256>>>(x, Wk, k, SEQ);
    gemm_nt<1><<<gg, 256>>>(x, Wv, v, SEQ);

    int tot = BH * SEQ * 32;
    rope_kernel<<<(tot + 255) / 256, 256>>>(q, k, BH, SEQ);

    const int SMEM = 4 * 64 * 68 * (int)sizeof(float);  // 69632
    cudaFuncSetAttribute(flash_kernel,
                         cudaFuncAttributeMaxDynamicSharedMemorySize, SMEM);
    flash_kernel<<<dim3(SEQ / 64, BH), 256, SMEM>>>(q, k, v, attn, SEQ);

    gemm_nt<0><<<gg, 256>>>(attn, Wo, (float*)d_out, SEQ);
}

// round 7
// speedup vs baseline: 1.1163x; 1.1163x over previous
#include <cuda_runtime.h>
#include <math.h>

#define D_MODEL 1024
#define N_HEADS 16
#define HEAD_DIM 64
#define SEQ 2048
#define MAXB 2

// Scratch (no allocations allowed)
__device__ float g_q[MAXB * N_HEADS * SEQ * HEAD_DIM];
__device__ float g_k[MAXB * N_HEADS * SEQ * HEAD_DIM];
__device__ float g_v[MAXB * N_HEADS * SEQ * HEAD_DIM];
__device__ float g_attn[MAXB * SEQ * D_MODEL];

// ---- packed fp32x2 helpers (SASS FFMA2 path, only reachable via PTX) ----
typedef unsigned long long u64;

__device__ __forceinline__ u64 pk2(float lo, float hi) {
    u64 r;
    asm("mov.b64 %0, {%1, %2};" : "=l"(r) : "f"(lo), "f"(hi));
    return r;
}
__device__ __forceinline__ void upk2(float& lo, float& hi, u64 v) {
    asm("mov.b64 {%0, %1}, %2;" : "=f"(lo), "=f"(hi) : "l"(v));
}
__device__ __forceinline__ u64 ffma2(u64 a, u64 b, u64 c) {
    u64 d;
    asm("fma.rn.f32x2 %0, %1, %2, %3;" : "=l"(d) : "l"(a), "l"(b), "l"(c));
    return d;
}
__device__ __forceinline__ u64 fmul2(u64 a, u64 b) {
    u64 d;
    asm("mul.rn.f32x2 %0, %1, %2;" : "=l"(d) : "l"(a), "l"(b));
    return d;
}

// ---------------------------------------------------------------------------
// GEMM: C = A (MxK) * W^T, W stored [N,K] row-major (torch Linear weights).
// K = N = D_MODEL = 1024. BM=BN=128, BK=16, 256 threads, 8x8 per thread.
// Inner product via packed f32x2 FFMA2: acc paired over adjacent M rows.
// QKV=1: three outputs selected by blockIdx.z, written [B,H,S,HD].
// QKV=0: single output, row-major [M, D_MODEL].
// ---------------------------------------------------------------------------
template <int QKV>
__global__ void __launch_bounds__(256) gemm_nt(const float* __restrict__ A,
                                               const float* __restrict__ W0,
                                               const float* __restrict__ W1,
                                               const float* __restrict__ W2,
                                               float* __restrict__ C0,
                                               float* __restrict__ C1,
                                               float* __restrict__ C2, int S) {
    const int BM = 128, BN = 128, BK = 16, PAD = 4;
    __shared__ float As[BK][BM + PAD];
    __shared__ float Bs[BK][BN + PAD];

    const float* W = W0;
    float* C = C0;
    if (QKV) {
        if (blockIdx.z == 1) { W = W1; C = C1; }
        else if (blockIdx.z == 2) { W = W2; C = C2; }
    }

    int tid = threadIdx.x;
    int tx = tid & 15;        // N groups of 8
    int ty = tid >> 4;        // M groups of 8
    int mBase = blockIdx.x * BM;
    int nBase = blockIdx.y * BN;

    // acc2[p][j]: pair of rows (ty*8+2p, ty*8+2p+1), column tx*8+j
    u64 acc2[4][8];
#pragma unroll
    for (int p = 0; p < 4; ++p)
#pragma unroll
        for (int j = 0; j < 8; ++j) acc2[p][j] = 0ull;

    for (int k0 = 0; k0 < D_MODEL; k0 += BK) {
#pragma unroll
        for (int it = 0; it < 8; ++it) {
            int e = it * 256 + tid;
            int m = e >> 4, kk = e & 15;
            As[kk][m] = A[(mBase + m) * D_MODEL + k0 + kk];
        }
#pragma unroll
        for (int it = 0; it < 8; ++it) {
            int e = it * 256 + tid;
            int n = e >> 4, kk = e & 15;
            Bs[kk][n] = W[(nBase + n) * D_MODEL + k0 + kk];
        }
        __syncthreads();

#pragma unroll
        for (int kk = 0; kk < BK; ++kk) {
            // a: 4 packed row-pairs, straight from smem (16B aligned)
            ulonglong2 a01 = *(const ulonglong2*)&As[kk][ty * 8];
            ulonglong2 a23 = *(const ulonglong2*)&As[kk][ty * 8 + 4];
            u64 ap[4] = {a01.x, a01.y, a23.x, a23.y};
            float4 b0 = *(const float4*)&Bs[kk][tx * 8];
            float4 b1 = *(const float4*)&Bs[kk][tx * 8 + 4];
            float bs[8] = {b0.x, b0.y, b0.z, b0.w, b1.x, b1.y, b1.z, b1.w};
#pragma unroll
            for (int j = 0; j < 8; ++j) {
                u64 bb = pk2(bs[j], bs[j]);
#pragma unroll
                for (int p = 0; p < 4; ++p)
                    acc2[p][j] = ffma2(ap[p], bb, acc2[p][j]);
            }
        }
        __syncthreads();
    }

#pragma unroll
    for (int p = 0; p < 4; ++p) {
#pragma unroll
        for (int j = 0; j < 8; ++j) {
            float lo, hi;
            upk2(lo, hi, acc2[p][j]);
            int col = nBase + tx * 8 + j;
            int t0 = mBase + ty * 8 + 2 * p;
            if (!QKV) {
                C[(size_t)t0 * D_MODEL + col] = lo;
                C[(size_t)(t0 + 1) * D_MODEL + col] = hi;
            } else {
                int h = col >> 6, hd = col & 63;
                {
                    int b = t0 / S, s = t0 - b * S;
                    C[(((size_t)b * N_HEADS + h) * S + s) * HEAD_DIM + hd] = lo;
                }
                {
                    int t1 = t0 + 1;
                    int b = t1 / S, s = t1 - b * S;
                    C[(((size_t)b * N_HEADS + h) * S + s) * HEAD_DIM + hd] = hi;
                }
            }
        }
    }
}

// ---------------------------------------------------------------------------
// RoPE on Q and K in-place. Layout [BH, S, HD]. One thread per (bh, s, pair).
// ---------------------------------------------------------------------------
__global__ void rope_kernel(float* __restrict__ q, float* __restrict__ k,
                            int BH, int S) {
    int idx = blockIdx.x * blockDim.x + threadIdx.x;
    int total = BH * S * 32;
    if (idx >= total) return;
    int j = idx & 31;
    int s = (idx >> 5) % S;
    int bh = idx / (32 * S);

    float inv = powf(10000.0f, -(float)j / 32.0f);
    float ang = (float)s * inv;
    float sn, cs;
    sincosf(ang, &sn, &cs);

    size_t base = ((size_t)bh * S + s) * HEAD_DIM;
    float q1 = q[base + j], q2 = q[base + j + 32];
    q[base + j]      = q1 * cs - q2 * sn;
    q[base + j + 32] = q2 * cs + q1 * sn;
    float k1 = k[base + j], k2 = k[base + j + 32];
    k[base + j]      = k1 * cs - k2 * sn;
    k[base + j + 32] = k2 * cs + k1 * sn;
}

// ---------------------------------------------------------------------------
// Flash attention, causal, fp32, FFMA2 inner loops.
// 64 queries per block, key tiles of 64. Grid: (S/64, B*H), 256 threads.
// ---------------------------------------------------------------------------
__global__ void __launch_bounds__(256) flash_kernel(const float* __restrict__ Q,
                                                    const float* __restrict__ K,
                                                    const float* __restrict__ V,
                                                    float* __restrict__ O, int S) {
    const int P = 68;   // 272B row pitch, 16B-aligned
    extern __shared__ float sm[];
    float* Qt = sm;                  // [64][68]  Qt[d][i]
    float* Kt = Qt + 64 * P;         // [64][68]  Kt[d][j]
    float* Vs = Kt + 64 * P;         // [64][68]  Vs[j][d]
    float* Pt = Vs + 64 * P;         // [64][68]  Pt[j][i]

    int tid = threadIdx.x;
    int tx = tid & 15;   // score col group / O col group
    int ty = tid >> 4;   // row group

    int qb = blockIdx.x * 64;
    int bh = blockIdx.y;
    const float* Qbase = Q + (size_t)bh * S * HEAD_DIM;
    const float* Kbase = K + (size_t)bh * S * HEAD_DIM;
    const float* Vbase = V + (size_t)bh * S * HEAD_DIM;

#pragma unroll
    for (int it = 0; it < 16; ++it) {
        int e = it * 256 + tid;
        int i = e >> 6, d = e & 63;
        Qt[d * P + i] = Qbase[(size_t)(qb + i) * HEAD_DIM + d] * 0.125f;
    }

    float m_i[4], l_i[4];
    u64 acc2[4][2];   // acc2[i][j2]: row i, column pair (tx*4+2*j2, +1)
#pragma unroll
    for (int i = 0; i < 4; ++i) {
        m_i[i] = -1e30f;
        l_i[i] = 0.0f;
        acc2[i][0] = 0ull;
        acc2[i][1] = 0ull;
    }

    int nkb = qb / 64 + 1;
    for (int kb = 0; kb < nkb; ++kb) {
        __syncthreads();
#pragma unroll
        for (int it = 0; it < 16; ++it) {
            int e = it * 256 + tid;
            int j = e >> 6, d = e & 63;
            size_t g = (size_t)(kb * 64 + j) * HEAD_DIM + d;
            Kt[d * P + j] = Kbase[g];
            Vs[j * P + d] = Vbase[g];
        }
        __syncthreads();

        // ---- scores S = Q * K^T (packed over key columns) ----
        u64 s2[4][2];
#pragma unroll
        for (int i = 0; i < 4; ++i) { s2[i][0] = 0ull; s2[i][1] = 0ull; }

#pragma unroll 8
        for (int kk = 0; kk < 64; ++kk) {
            float4 av = *(const float4*)&Qt[kk * P + ty * 4];
            ulonglong2 bv = *(const ulonglong2*)&Kt[kk * P + tx * 4];
            float a[4] = {av.x, av.y, av.z, av.w};
#pragma unroll
            for (int i = 0; i < 4; ++i) {
                u64 aa = pk2(a[i], a[i]);
                s2[i][0] = ffma2(aa, bv.x, s2[i][0]);
                s2[i][1] = ffma2(aa, bv.y, s2[i][1]);
            }
        }

        float s[4][4];
#pragma unroll
        for (int i = 0; i < 4; ++i) {
            upk2(s[i][0], s[i][1], s2[i][0]);
            upk2(s[i][2], s[i][3], s2[i][1]);
        }

        // ---- causal mask (diagonal block only) ----
        if (kb == qb / 64) {
#pragma unroll
            for (int i = 0; i < 4; ++i)
#pragma unroll
                for (int j = 0; j < 4; ++j)
                    if (kb * 64 + tx * 4 + j > qb + ty * 4 + i) s[i][j] = -1e30f;
        }

        // ---- online softmax ----
        float al[4];
#pragma unroll
        for (int i = 0; i < 4; ++i) {
            float mm = fmaxf(fmaxf(s[i][0], s[i][1]), fmaxf(s[i][2], s[i][3]));
#pragma unroll
            for (int off = 8; off > 0; off >>= 1)
                mm = fmaxf(mm, __shfl_xor_sync(0xffffffffu, mm, off));
            float mn = fmaxf(m_i[i], mm);
            al[i] = __expf(m_i[i] - mn);
            m_i[i] = mn;
            float sum = 0.0f;
#pragma unroll
            for (int j = 0; j < 4; ++j) {
                float p = __expf(s[i][j] - mn);
                Pt[(tx * 4 + j) * P + ty * 4 + i] = p;
                sum += p;
            }
#pragma unroll
            for (int off = 8; off > 0; off >>= 1)
                sum += __shfl_xor_sync(0xffffffffu, sum, off);
            l_i[i] = l_i[i] * al[i] + sum;
        }
        __syncthreads();

        // ---- O = O*alpha + P * V ----
#pragma unroll
        for (int i = 0; i < 4; ++i) {
            u64 av = pk2(al[i], al[i]);
            acc2[i][0] = fmul2(acc2[i][0], av);
            acc2[i][1] = fmul2(acc2[i][1], av);
        }

#pragma unroll 8
        for (int kk = 0; kk < 64; ++kk) {
            float4 av = *(const float4*)&Pt[kk * P + ty * 4];
            ulonglong2 bv = *(const ulonglong2*)&Vs[kk * P + tx * 4];
            float a[4] = {av.x, av.y, av.z, av.w};
#pragma unroll
            for (int i = 0; i < 4; ++i) {
                u64 aa = pk2(a[i], a[i]);
                acc2[i][0] = ffma2(aa, bv.x, acc2[i][0]);
                acc2[i][1] = ffma2(aa, bv.y, acc2[i][1]);
            }
        }
    }

    // write out: [B, S, H*HD] so final projection sees contiguous [T, D]
    int b = bh / N_HEADS, h = bh % N_HEADS;
#pragma unroll
    for (int i = 0; i < 4; ++i) {
        int t = qb + ty * 4 + i;
        float inv_l = 1.0f / l_i[i];
        float o[4];
        upk2(o[0], o[1], acc2[i][0]);
        upk2(o[2], o[3], acc2[i][1]);
        size_t base = ((size_t)b * S + t) * D_MODEL + h * HEAD_DIM + tx * 4;
#pragma unroll
        for (int j = 0; j < 4; ++j) O[base + j] = o[j] * inv_l;
    }
}

// ---------------------------------------------------------------------------
extern "C" void kernel_launch(void* const* d_in, const int* in_sizes, int n_in,
                              void* d_out, int out_size) {
    const float* x  = (const float*)d_in[0];
    const float* Wq = (const float*)d_in[1];
    const float* Wk = (const float*)d_in[2];
    const float* Wv = (const float*)d_in[3];
    const float* Wo = (const float*)d_in[4];

    int B = in_sizes[0] / (SEQ * D_MODEL);
    if (B < 1) B = 1;
    if (B > MAXB) B = MAXB;
    int T = B * SEQ;
    int BH = B * N_HEADS;

    float *q, *k, *v, *attn;
    cudaGetSymbolAddress((void**)&q, g_q);
    cudaGetSymbolAddress((void**)&k, g_k);
    cudaGetSymbolAddress((void**)&v, g_v);
    cudaGetSymbolAddress((void**)&attn, g_attn);

    // fused QKV projection: one launch, grid.z selects Wq/Wk/Wv
    dim3 gqkv(T / 128, D_MODEL / 128, 3);
    gemm_nt<1><<<gqkv, 256>>>(x, Wq, Wk, Wv, q, k, v, SEQ);

    int tot = BH * SEQ * 32;
    rope_kernel<<<(tot + 255) / 256, 256>>>(q, k, BH, SEQ);

    const int SMEM = 4 * 64 * 68 * (int)sizeof(float);  // 69632
    cudaFuncSetAttribute(flash_kernel,
                         cudaFuncAttributeMaxDynamicSharedMemorySize, SMEM);
    flash_kernel<<<dim3(SEQ / 64, BH), 256, SMEM>>>(q, k, v, attn, SEQ);

    dim3 go(T / 128, D_MODEL / 128, 1);
    gemm_nt<0><<<go, 256>>>(attn, Wo, nullptr, nullptr, (float*)d_out,
                            nullptr, nullptr, SEQ);
}

// round 9
// speedup vs baseline: 1.2857x; 1.1518x over previous
#include <cuda_runtime.h>
#include <math.h>
#include <stdint.h>

#define D_MODEL 1024
#define N_HEADS 16
#define HEAD_DIM 64
#define SEQ 2048
#define MAXB 2

// ---------------- scratch (no allocations allowed) ----------------
__device__ __align__(1024) float g_q[MAXB * N_HEADS * SEQ * HEAD_DIM];
__device__ __align__(1024) float g_k[MAXB * N_HEADS * SEQ * HEAD_DIM];
__device__ __align__(1024) float g_v[MAXB * N_HEADS * SEQ * HEAD_DIM];
__device__ __align__(1024) float g_attn[MAXB * SEQ * D_MODEL];
__device__ __align__(1024) float g_xh[MAXB * SEQ * D_MODEL];   // hi split of x / attn
__device__ __align__(1024) float g_xl[MAXB * SEQ * D_MODEL];   // lo split of x / attn
__device__ __align__(1024) float g_wh[4 * D_MODEL * D_MODEL];  // hi split of Wq,Wk,Wv,Wo
__device__ __align__(1024) float g_wl[4 * D_MODEL * D_MODEL];

// ---------------- helpers ----------------
typedef unsigned long long u64;

__device__ __forceinline__ uint32_t stou(const void* p) {
    uint32_t a;
    asm("{ .reg .u64 t; cvta.to.shared.u64 t, %1; cvt.u32.u64 %0, t; }"
        : "=r"(a) : "l"(p));
    return a;
}
__device__ __forceinline__ float tf32r(float x) {
    float r;
    asm("cvt.rna.tf32.f32 %0, %1;" : "=f"(r) : "f"(x));
    return r;
}
__device__ __forceinline__ u64 pk2(float lo, float hi) {
    u64 r;
    asm("mov.b64 %0, {%1, %2};" : "=l"(r) : "f"(lo), "f"(hi));
    return r;
}
__device__ __forceinline__ void upk2(float& lo, float& hi, u64 v) {
    asm("mov.b64 {%0, %1}, %2;" : "=f"(lo), "=f"(hi) : "l"(v));
}
__device__ __forceinline__ u64 ffma2(u64 a, u64 b, u64 c) {
    u64 d;
    asm("fma.rn.f32x2 %0, %1, %2, %3;" : "=l"(d) : "l"(a), "l"(b), "l"(c));
    return d;
}
__device__ __forceinline__ u64 fmul2(u64 a, u64 b) {
    u64 d;
    asm("mul.rn.f32x2 %0, %1, %2;" : "=l"(d) : "l"(a), "l"(b));
    return d;
}

__device__ __forceinline__ void cpasync16(uint32_t dst, const void* src) {
    asm volatile("cp.async.cg.shared.global [%0], [%1], 16;"
                 :: "r"(dst), "l"(src) : "memory");
}
#define CP_COMMIT() asm volatile("cp.async.commit_group;" ::: "memory")
#define CP_WAIT1()  asm volatile("cp.async.wait_group 1;" ::: "memory")
#define CP_WAIT0()  asm volatile("cp.async.wait_group 0;" ::: "memory")

__device__ __forceinline__ void mma_tf32(float c[4], const uint32_t a[4],
                                         const uint32_t b[2]) {
    asm volatile(
        "mma.sync.aligned.m16n8k8.row.col.f32.tf32.tf32.f32 "
        "{%0,%1,%2,%3}, {%4,%5,%6,%7}, {%8,%9}, {%0,%1,%2,%3};"
        : "+f"(c[0]), "+f"(c[1]), "+f"(c[2]), "+f"(c[3])
        : "r"(a[0]), "r"(a[1]), "r"(a[2]), "r"(a[3]), "r"(b[0]), "r"(b[1]));
}

// ---------------- split kernels (fp32 -> tf32 hi + tf32 lo) ----------------
__global__ void split_kernel(const float4* __restrict__ src, float4* __restrict__ hi,
                             float4* __restrict__ lo, int n4) {
    int i = blockIdx.x * 256 + threadIdx.x;
    if (i >= n4) return;
    float4 v = src[i], h, l;
    h.x = tf32r(v.x); l.x = tf32r(v.x - h.x);
    h.y = tf32r(v.y); l.y = tf32r(v.y - h.y);
    h.z = tf32r(v.z); l.z = tf32r(v.z - h.z);
    h.w = tf32r(v.w); l.w = tf32r(v.w - h.w);
    hi[i] = h; lo[i] = l;
}

__global__ void splitw_kernel(const float* __restrict__ w0, const float* __restrict__ w1,
                              const float* __restrict__ w2, const float* __restrict__ w3,
                              float* __restrict__ hi, float* __restrict__ lo) {
    int y = blockIdx.y;
    const float* w = (y == 0) ? w0 : (y == 1) ? w1 : (y == 2) ? w2 : w3;
    const int n4 = (D_MODEL * D_MODEL) / 4;
    const float4* s4 = (const float4*)w;
    float4* h4 = (float4*)(hi + (size_t)y * D_MODEL * D_MODEL);
    float4* l4 = (float4*)(lo + (size_t)y * D_MODEL * D_MODEL);
    for (int i = blockIdx.x * 256 + threadIdx.x; i < n4; i += gridDim.x * 256) {
        float4 v = s4[i], h, l;
        h.x = tf32r(v.x); l.x = tf32r(v.x - h.x);
        h.y = tf32r(v.y); l.y = tf32r(v.y - h.y);
        h.z = tf32r(v.z); l.z = tf32r(v.z - h.z);
        h.w = tf32r(v.w); l.w = tf32r(v.w - h.w);
        h4[i] = h; l4[i] = l;
    }
}

// ---------------------------------------------------------------------------
// mma.sync tf32 GEMM, split precision: D = Ah*Bh^T + Al*Bh^T + Ah*Bl^T.
// C = A(TxK) * W^T, W [N,K] row-major. Tile 128x128, BK=16, 8 warps (2x4),
// warp tile 64x32 via m16n8k8. cp.async double-buffered.
// QKV=1: grid.z selects W/out (epilogue [B,H,S,HD]); QKV=0: row-major out.
// ---------------------------------------------------------------------------
#define PITCH 20                 // 16 + 4 pad floats
#define OPF (128 * PITCH)        // floats per operand tile = 2560
#define BUFF (4 * OPF)           // floats per buffer = 10240
#define NCHUNK (D_MODEL / 16)    // 64

template <int QKV>
__global__ void __launch_bounds__(256, 1) tc_gemm(
    const float* __restrict__ Ah, const float* __restrict__ Al,
    const float* __restrict__ Wh, const float* __restrict__ Wl,
    float* __restrict__ C0, float* __restrict__ C1, float* __restrict__ C2,
    int S) {
    extern __shared__ float sm[];

    int tid = threadIdx.x;
    int lane = tid & 31;
    int wid = tid >> 5;
    int warp_m = wid >> 2;            // 0..1
    int warp_n = wid & 3;             // 0..3

    int mBase = blockIdx.x * 128;
    int nBase = blockIdx.y * 128;

    const float* Bh = Wh;
    const float* Bl = Wl;
    float* C = C0;
    if (QKV) {
        size_t woff = (size_t)blockIdx.z * D_MODEL * D_MODEL;
        Bh = Wh + woff; Bl = Wl + woff;
        if (blockIdx.z == 1) C = C1;
        else if (blockIdx.z == 2) C = C2;
    }

    uint32_t sbase = stou(sm);

    // staging: per chunk, 4 operands x 512 float4; thread does 2 float4/operand
    int m_a = tid >> 2;               // rows 0..63 (it adds 64)
    int kq = tid & 3;
    const float* gAh = Ah + (size_t)(mBase + m_a) * D_MODEL + kq * 4;
    const float* gAl = Al + (size_t)(mBase + m_a) * D_MODEL + kq * 4;
    const float* gBh = Bh + (size_t)(nBase + m_a) * D_MODEL + kq * 4;
    const float* gBl = Bl + (size_t)(nBase + m_a) * D_MODEL + kq * 4;
    uint32_t sdst0 = (uint32_t)(m_a * PITCH + kq * 4) * 4u;
    const uint32_t rowStep = 64 * PITCH * 4;   // +64 rows in bytes
    const size_t gRowStep = (size_t)64 * D_MODEL;

#define STAGE(buf, k0)                                                         \
    do {                                                                       \
        uint32_t sb = sbase + (uint32_t)(buf) * (BUFF * 4) + sdst0;            \
        const float* pa_h = gAh + (k0);                                        \
        const float* pa_l = gAl + (k0);                                        \
        const float* pb_h = gBh + (k0);                                        \
        const float* pb_l = gBl + (k0);                                        \
        cpasync16(sb,                         pa_h);                           \
        cpasync16(sb + rowStep,               pa_h + gRowStep);                \
        cpasync16(sb + OPF * 4,               pa_l);                           \
        cpasync16(sb + OPF * 4 + rowStep,     pa_l + gRowStep);                \
        cpasync16(sb + 2 * OPF * 4,           pb_h);                           \
        cpasync16(sb + 2 * OPF * 4 + rowStep, pb_h + gRowStep);                \
        cpasync16(sb + 3 * OPF * 4,           pb_l);                           \
        cpasync16(sb + 3 * OPF * 4 + rowStep, pb_l + gRowStep);                \
    } while (0)

    float c[4][4][4];
#pragma unroll
    for (int mi = 0; mi < 4; ++mi)
#pragma unroll
        for (int ni = 0; ni < 4; ++ni)
#pragma unroll
            for (int r = 0; r < 4; ++r) c[mi][ni][r] = 0.0f;

    int aBase = (warp_m * 64 + (lane >> 2)) * PITCH + (lane & 3);
    int bBase = (warp_n * 32 + (lane >> 2)) * PITCH + (lane & 3);

    STAGE(0, 0);
    CP_COMMIT();

    for (int ch = 0; ch < NCHUNK; ++ch) {
        if (ch + 1 < NCHUNK) {
            STAGE((ch + 1) & 1, (ch + 1) * 16);
            CP_COMMIT();
            CP_WAIT1();
        } else {
            CP_WAIT0();
        }
        __syncthreads();

        const uint32_t* sAh = (const uint32_t*)(sm + (ch & 1) * BUFF);
        const uint32_t* sAl = sAh + OPF;
        const uint32_t* sBh = sAl + OPF;
        const uint32_t* sBl = sBh + OPF;

#pragma unroll
        for (int ks = 0; ks < 2; ++ks) {
            const int kb = ks * 8;
            uint32_t ah[4][4], al[4][4], bh[4][2], bl[4][2];
#pragma unroll
            for (int mi = 0; mi < 4; ++mi) {
                int o = aBase + mi * (16 * PITCH) + kb;
                ah[mi][0] = sAh[o];
                ah[mi][1] = sAh[o + 8 * PITCH];
                ah[mi][2] = sAh[o + 4];
                ah[mi][3] = sAh[o + 8 * PITCH + 4];
                al[mi][0] = sAl[o];
                al[mi][1] = sAl[o + 8 * PITCH];
                al[mi][2] = sAl[o + 4];
                al[mi][3] = sAl[o + 8 * PITCH + 4];
            }
#pragma unroll
            for (int ni = 0; ni < 4; ++ni) {
                int o = bBase + ni * (8 * PITCH) + kb;
                bh[ni][0] = sBh[o];
                bh[ni][1] = sBh[o + 4];
                bl[ni][0] = sBl[o];
                bl[ni][1] = sBl[o + 4];
            }
#pragma unroll
            for (int mi = 0; mi < 4; ++mi)
#pragma unroll
                for (int ni = 0; ni < 4; ++ni) {
                    mma_tf32(c[mi][ni], ah[mi], bh[ni]);
                    mma_tf32(c[mi][ni], al[mi], bh[ni]);
                    mma_tf32(c[mi][ni], ah[mi], bl[ni]);
                }
        }
        __syncthreads();
    }
#undef STAGE

    // epilogue
#pragma unroll
    for (int mi = 0; mi < 4; ++mi) {
#pragma unroll
        for (int ni = 0; ni < 4; ++ni) {
            int r0 = mBase + warp_m * 64 + mi * 16 + (lane >> 2);
            int cc = nBase + warp_n * 32 + ni * 8 + 2 * (lane & 3);
            float2 v0 = make_float2(c[mi][ni][0], c[mi][ni][1]);
            float2 v1 = make_float2(c[mi][ni][2], c[mi][ni][3]);
            if (!QKV) {
                *(float2*)(C + (size_t)r0 * D_MODEL + cc) = v0;
                *(float2*)(C + (size_t)(r0 + 8) * D_MODEL + cc) = v1;
            } else {
                int h = cc >> 6, hd = cc & 63;
                int b0 = r0 / S, s0 = r0 - b0 * S;
                *(float2*)(C + (((size_t)b0 * N_HEADS + h) * S + s0) * HEAD_DIM + hd) = v0;
                int r1 = r0 + 8;
                int b1 = r1 / S, s1 = r1 - b1 * S;
                *(float2*)(C + (((size_t)b1 * N_HEADS + h) * S + s1) * HEAD_DIM + hd) = v1;
            }
        }
    }
}

// ---------------------------------------------------------------------------
// RoPE on Q and K in-place. Layout [BH, S, HD].
// ---------------------------------------------------------------------------
__global__ void rope_kernel(float* __restrict__ q, float* __restrict__ k,
                            int BH, int S) {
    int idx = blockIdx.x * blockDim.x + threadIdx.x;
    int total = BH * S * 32;
    if (idx >= total) return;
    int j = idx & 31;
    int s = (idx >> 5) % S;
    int bh = idx / (32 * S);

    float inv = powf(10000.0f, -(float)j / 32.0f);
    float ang = (float)s * inv;
    float sn, cs;
    sincosf(ang, &sn, &cs);

    size_t base = ((size_t)bh * S + s) * HEAD_DIM;
    float q1 = q[base + j], q2 = q[base + j + 32];
    q[base + j]      = q1 * cs - q2 * sn;
    q[base + j + 32] = q2 * cs + q1 * sn;
    float k1 = k[base + j], k2 = k[base + j + 32];
    k[base + j]      = k1 * cs - k2 * sn;
    k[base + j + 32] = k2 * cs + k1 * sn;
}

// ---------------------------------------------------------------------------
// Flash attention, causal, fp32, FFMA2 inner loops (unchanged).
// ---------------------------------------------------------------------------
__global__ void __launch_bounds__(256) flash_kernel(const float* __restrict__ Q,
                                                    const float* __restrict__ K,
                                                    const float* __restrict__ V,
                                                    float* __restrict__ O, int S) {
    const int P = 68;
    extern __shared__ float smf[];
    float* Qt = smf;
    float* Kt = Qt + 64 * P;
    float* Vs = Kt + 64 * P;
    float* Pt = Vs + 64 * P;

    int tid = threadIdx.x;
    int tx = tid & 15;
    int ty = tid >> 4;

    int qb = blockIdx.x * 64;
    int bh = blockIdx.y;
    const float* Qbase = Q + (size_t)bh * S * HEAD_DIM;
    const float* Kbase = K + (size_t)bh * S * HEAD_DIM;
    const float* Vbase = V + (size_t)bh * S * HEAD_DIM;

#pragma unroll
    for (int it = 0; it < 16; ++it) {
        int e = it * 256 + tid;
        int i = e >> 6, d = e & 63;
        Qt[d * P + i] = Qbase[(size_t)(qb + i) * HEAD_DIM + d] * 0.125f;
    }

    float m_i[4], l_i[4];
    u64 acc2[4][2];
#pragma unroll
    for (int i = 0; i < 4; ++i) {
        m_i[i] = -1e30f;
        l_i[i] = 0.0f;
        acc2[i][0] = 0ull;
        acc2[i][1] = 0ull;
    }

    int nkb = qb / 64 + 1;
    for (int kb = 0; kb < nkb; ++kb) {
        __syncthreads();
#pragma unroll
        for (int it = 0; it < 16; ++it) {
            int e = it * 256 + tid;
            int j = e >> 6, d = e & 63;
            size_t g = (size_t)(kb * 64 + j) * HEAD_DIM + d;
            Kt[d * P + j] = Kbase[g];
            Vs[j * P + d] = Vbase[g];
        }
        __syncthreads();

        u64 s2[4][2];
#pragma unroll
        for (int i = 0; i < 4; ++i) { s2[i][0] = 0ull; s2[i][1] = 0ull; }

#pragma unroll 8
        for (int kk = 0; kk < 64; ++kk) {
            float4 av = *(const float4*)&Qt[kk * P + ty * 4];
            ulonglong2 bv = *(const ulonglong2*)&Kt[kk * P + tx * 4];
            float a[4] = {av.x, av.y, av.z, av.w};
#pragma unroll
            for (int i = 0; i < 4; ++i) {
                u64 aa = pk2(a[i], a[i]);
                s2[i][0] = ffma2(aa, bv.x, s2[i][0]);
                s2[i][1] = ffma2(aa, bv.y, s2[i][1]);
            }
        }

        float s[4][4];
#pragma unroll
        for (int i = 0; i < 4; ++i) {
            upk2(s[i][0], s[i][1], s2[i][0]);
            upk2(s[i][2], s[i][3], s2[i][1]);
        }

        if (kb == qb / 64) {
#pragma unroll
            for (int i = 0; i < 4; ++i)
#pragma unroll
                for (int j = 0; j < 4; ++j)
                    if (kb * 64 + tx * 4 + j > qb + ty * 4 + i) s[i][j] = -1e30f;
        }

        float al[4];
#pragma unroll
        for (int i = 0; i < 4; ++i) {
            float mm = fmaxf(fmaxf(s[i][0], s[i][1]), fmaxf(s[i][2], s[i][3]));
#pragma unroll
            for (int off = 8; off > 0; off >>= 1)
                mm = fmaxf(mm, __shfl_xor_sync(0xffffffffu, mm, off));
            float mn = fmaxf(m_i[i], mm);
            al[i] = __expf(m_i[i] - mn);
            m_i[i] = mn;
            float sum = 0.0f;
#pragma unroll
            for (int j = 0; j < 4; ++j) {
                float p = __expf(s[i][j] - mn);
                Pt[(tx * 4 + j) * P + ty * 4 + i] = p;
                sum += p;
            }
#pragma unroll
            for (int off = 8; off > 0; off >>= 1)
                sum += __shfl_xor_sync(0xffffffffu, sum, off);
            l_i[i] = l_i[i] * al[i] + sum;
        }
        __syncthreads();

#pragma unroll
        for (int i = 0; i < 4; ++i) {
            u64 av = pk2(al[i], al[i]);
            acc2[i][0] = fmul2(acc2[i][0], av);
            acc2[i][1] = fmul2(acc2[i][1], av);
        }

#pragma unroll 8
        for (int kk = 0; kk < 64; ++kk) {
            float4 av = *(const float4*)&Pt[kk * P + ty * 4];
            ulonglong2 bv = *(const ulonglong2*)&Vs[kk * P + tx * 4];
            float a[4] = {av.x, av.y, av.z, av.w};
#pragma unroll
            for (int i = 0; i < 4; ++i) {
                u64 aa = pk2(a[i], a[i]);
                acc2[i][0] = ffma2(aa, bv.x, acc2[i][0]);
                acc2[i][1] = ffma2(aa, bv.y, acc2[i][1]);
            }
        }
    }

    int b = bh / N_HEADS, h = bh % N_HEADS;
#pragma unroll
    for (int i = 0; i < 4; ++i) {
        int t = qb + ty * 4 + i;
        float inv_l = 1.0f / l_i[i];
        float o[4];
        upk2(o[0], o[1], acc2[i][0]);
        upk2(o[2], o[3], acc2[i][1]);
        size_t base = ((size_t)b * S + t) * D_MODEL + h * HEAD_DIM + tx * 4;
#pragma unroll
        for (int j = 0; j < 4; ++j) O[base + j] = o[j] * inv_l;
    }
}

// ---------------- host side ----------------
extern "C" void kernel_launch(void* const* d_in, const int* in_sizes, int n_in,
                              void* d_out, int out_size) {
    const float* x  = (const float*)d_in[0];
    const float* Wq = (const float*)d_in[1];
    const float* Wk = (const float*)d_in[2];
    const float* Wv = (const float*)d_in[3];
    const float* Wo = (const float*)d_in[4];

    int B = in_sizes[0] / (SEQ * D_MODEL);
    if (B < 1) B = 1;
    if (B > MAXB) B = MAXB;
    int T = B * SEQ;
    int BH = B * N_HEADS;

    float *q, *k, *v, *attn, *xh, *xl, *wh, *wl;
    cudaGetSymbolAddress((void**)&q, g_q);
    cudaGetSymbolAddress((void**)&k, g_k);
    cudaGetSymbolAddress((void**)&v, g_v);
    cudaGetSymbolAddress((void**)&attn, g_attn);
    cudaGetSymbolAddress((void**)&xh, g_xh);
    cudaGetSymbolAddress((void**)&xl, g_xl);
    cudaGetSymbolAddress((void**)&wh, g_wh);
    cudaGetSymbolAddress((void**)&wl, g_wl);

    const int GSMEM = 2 * BUFF * (int)sizeof(float);   // 81920
    cudaFuncSetAttribute(tc_gemm<1>, cudaFuncAttributeMaxDynamicSharedMemorySize, GSMEM);
    cudaFuncSetAttribute(tc_gemm<0>, cudaFuncAttributeMaxDynamicSharedMemorySize, GSMEM);

    const size_t WSZ = (size_t)D_MODEL * D_MODEL;

    // 1) split x and weights into tf32 hi/lo
    int n4 = T * D_MODEL / 4;
    split_kernel<<<(n4 + 255) / 256, 256>>>((const float4*)x, (float4*)xh, (float4*)xl, n4);
    splitw_kernel<<<dim3(256, 4), 256>>>(Wq, Wk, Wv, Wo, wh, wl);

    // 2) QKV projections on tensor cores (grid.z selects Wq/Wk/Wv slice)
    tc_gemm<1><<<dim3(T / 128, D_MODEL / 128, 3), 256, GSMEM>>>(
        xh, xl, wh, wl, q, k, v, SEQ);

    // 3) RoPE
    int tot = BH * SEQ * 32;
    rope_kernel<<<(tot + 255) / 256, 256>>>(q, k, BH, SEQ);

    // 4) flash attention
    const int SMEM = 4 * 64 * 68 * (int)sizeof(float);
    cudaFuncSetAttribute(flash_kernel, cudaFuncAttributeMaxDynamicSharedMemorySize, SMEM);
    flash_kernel<<<dim3(SEQ / 64, BH), 256, SMEM>>>(q, k, v, attn, SEQ);

    // 5) split attn, then output projection on tensor cores
    split_kernel<<<(n4 + 255) / 256, 256>>>((const float4*)attn, (float4*)xh, (float4*)xl, n4);
    tc_gemm<0><<<dim3(T / 128, D_MODEL / 128, 1), 256, GSMEM>>>(
        xh, xl, wh + 3 * WSZ, wl + 3 * WSZ, (float*)d_out, nullptr, nullptr, SEQ);
}

// round 10
// speedup vs baseline: 1.5907x; 1.2372x over previous
#include <cuda_runtime.h>
#include <math.h>
#include <stdint.h>

#define D_MODEL 1024
#define N_HEADS 16
#define HEAD_DIM 64
#define SEQ 2048
#define MAXB 2

// ---------------- scratch (no allocations allowed) ----------------
__device__ __align__(1024) float g_q[MAXB * N_HEADS * SEQ * HEAD_DIM];
__device__ __align__(1024) float g_k[MAXB * N_HEADS * SEQ * HEAD_DIM];
__device__ __align__(1024) float g_v[MAXB * N_HEADS * SEQ * HEAD_DIM];
__device__ __align__(1024) float g_xh[MAXB * SEQ * D_MODEL];   // hi split of x / attn-out
__device__ __align__(1024) float g_xl[MAXB * SEQ * D_MODEL];   // lo split
__device__ __align__(1024) float g_wh[4 * D_MODEL * D_MODEL];  // hi split of Wq,Wk,Wv,Wo
__device__ __align__(1024) float g_wl[4 * D_MODEL * D_MODEL];

// ---------------- helpers ----------------
__device__ __forceinline__ uint32_t stou(const void* p) {
    uint32_t a;
    asm("{ .reg .u64 t; cvta.to.shared.u64 t, %1; cvt.u32.u64 %0, t; }"
        : "=r"(a) : "l"(p));
    return a;
}
__device__ __forceinline__ float tf32r(float x) {
    float r;
    asm("cvt.rna.tf32.f32 %0, %1;" : "=f"(r) : "f"(x));
    return r;
}
__device__ __forceinline__ void cpasync16(uint32_t dst, const void* src) {
    asm volatile("cp.async.cg.shared.global [%0], [%1], 16;"
                 :: "r"(dst), "l"(src) : "memory");
}
#define CP_COMMIT() asm volatile("cp.async.commit_group;" ::: "memory")
#define CP_WAIT1()  asm volatile("cp.async.wait_group 1;" ::: "memory")
#define CP_WAIT0()  asm volatile("cp.async.wait_group 0;" ::: "memory")

__device__ __forceinline__ void mma_tf32(float c[4], const uint32_t a[4],
                                         const uint32_t b[2]) {
    asm volatile(
        "mma.sync.aligned.m16n8k8.row.col.f32.tf32.tf32.f32 "
        "{%0,%1,%2,%3}, {%4,%5,%6,%7}, {%8,%9}, {%0,%1,%2,%3};"
        : "+f"(c[0]), "+f"(c[1]), "+f"(c[2]), "+f"(c[3])
        : "r"(a[0]), "r"(a[1]), "r"(a[2]), "r"(a[3]), "r"(b[0]), "r"(b[1]));
}

// ---------------- split kernels (fp32 -> tf32 hi + residual lo) ----------------
__global__ void split_kernel(const float4* __restrict__ src, float4* __restrict__ hi,
                             float4* __restrict__ lo, int n4) {
    int i = blockIdx.x * 256 + threadIdx.x;
    if (i >= n4) return;
    float4 v = src[i], h, l;
    h.x = tf32r(v.x); l.x = v.x - h.x;
    h.y = tf32r(v.y); l.y = v.y - h.y;
    h.z = tf32r(v.z); l.z = v.z - h.z;
    h.w = tf32r(v.w); l.w = v.w - h.w;
    hi[i] = h; lo[i] = l;
}

__global__ void splitw_kernel(const float* __restrict__ w0, const float* __restrict__ w1,
                              const float* __restrict__ w2, const float* __restrict__ w3,
                              float* __restrict__ hi, float* __restrict__ lo) {
    int y = blockIdx.y;
    const float* w = (y == 0) ? w0 : (y == 1) ? w1 : (y == 2) ? w2 : w3;
    const int n4 = (D_MODEL * D_MODEL) / 4;
    const float4* s4 = (const float4*)w;
    float4* h4 = (float4*)(hi + (size_t)y * D_MODEL * D_MODEL);
    float4* l4 = (float4*)(lo + (size_t)y * D_MODEL * D_MODEL);
    for (int i = blockIdx.x * 256 + threadIdx.x; i < n4; i += gridDim.x * 256) {
        float4 v = s4[i], h, l;
        h.x = tf32r(v.x); l.x = v.x - h.x;
        h.y = tf32r(v.y); l.y = v.y - h.y;
        h.z = tf32r(v.z); l.z = v.z - h.z;
        h.w = tf32r(v.w); l.w = v.w - h.w;
        h4[i] = h; l4[i] = l;
    }
}

// ---------------------------------------------------------------------------
// mma.sync tf32 GEMM (unchanged, passing): D = Ah*Bh^T + Al*Bh^T + Ah*Bl^T.
// ---------------------------------------------------------------------------
#define PITCH 20
#define OPF (128 * PITCH)
#define BUFF (4 * OPF)
#define NCHUNK (D_MODEL / 16)

template <int QKV>
__global__ void __launch_bounds__(256, 1) tc_gemm(
    const float* __restrict__ Ah, const float* __restrict__ Al,
    const float* __restrict__ Wh, const float* __restrict__ Wl,
    float* __restrict__ C0, float* __restrict__ C1, float* __restrict__ C2,
    int S) {
    extern __shared__ float sm[];

    int tid = threadIdx.x;
    int lane = tid & 31;
    int wid = tid >> 5;
    int warp_m = wid >> 2;
    int warp_n = wid & 3;

    int mBase = blockIdx.x * 128;
    int nBase = blockIdx.y * 128;

    const float* Bh = Wh;
    const float* Bl = Wl;
    float* C = C0;
    if (QKV) {
        size_t woff = (size_t)blockIdx.z * D_MODEL * D_MODEL;
        Bh = Wh + woff; Bl = Wl + woff;
        if (blockIdx.z == 1) C = C1;
        else if (blockIdx.z == 2) C = C2;
    }

    uint32_t sbase = stou(sm);

    int m_a = tid >> 2;
    int kq = tid & 3;
    const float* gAh = Ah + (size_t)(mBase + m_a) * D_MODEL + kq * 4;
    const float* gAl = Al + (size_t)(mBase + m_a) * D_MODEL + kq * 4;
    const float* gBh = Bh + (size_t)(nBase + m_a) * D_MODEL + kq * 4;
    const float* gBl = Bl + (size_t)(nBase + m_a) * D_MODEL + kq * 4;
    uint32_t sdst0 = (uint32_t)(m_a * PITCH + kq * 4) * 4u;
    const uint32_t rowStep = 64 * PITCH * 4;
    const size_t gRowStep = (size_t)64 * D_MODEL;

#define STAGE(buf, k0)                                                         \
    do {                                                                       \
        uint32_t sb = sbase + (uint32_t)(buf) * (BUFF * 4) + sdst0;            \
        const float* pa_h = gAh + (k0);                                        \
        const float* pa_l = gAl + (k0);                                        \
        const float* pb_h = gBh + (k0);                                        \
        const float* pb_l = gBl + (k0);                                        \
        cpasync16(sb,                         pa_h);                           \
        cpasync16(sb + rowStep,               pa_h + gRowStep);                \
        cpasync16(sb + OPF * 4,               pa_l);                           \
        cpasync16(sb + OPF * 4 + rowStep,     pa_l + gRowStep);                \
        cpasync16(sb + 2 * OPF * 4,           pb_h);                           \
        cpasync16(sb + 2 * OPF * 4 + rowStep, pb_h + gRowStep);                \
        cpasync16(sb + 3 * OPF * 4,           pb_l);                           \
        cpasync16(sb + 3 * OPF * 4 + rowStep, pb_l + gRowStep);                \
    } while (0)

    float c[4][4][4];
#pragma unroll
    for (int mi = 0; mi < 4; ++mi)
#pragma unroll
        for (int ni = 0; ni < 4; ++ni)
#pragma unroll
            for (int r = 0; r < 4; ++r) c[mi][ni][r] = 0.0f;

    int aBase = (warp_m * 64 + (lane >> 2)) * PITCH + (lane & 3);
    int bBase = (warp_n * 32 + (lane >> 2)) * PITCH + (lane & 3);

    STAGE(0, 0);
    CP_COMMIT();

    for (int ch = 0; ch < NCHUNK; ++ch) {
        if (ch + 1 < NCHUNK) {
            STAGE((ch + 1) & 1, (ch + 1) * 16);
            CP_COMMIT();
            CP_WAIT1();
        } else {
            CP_WAIT0();
        }
        __syncthreads();

        const uint32_t* sAh = (const uint32_t*)(sm + (ch & 1) * BUFF);
        const uint32_t* sAl = sAh + OPF;
        const uint32_t* sBh = sAl + OPF;
        const uint32_t* sBl = sBh + OPF;

#pragma unroll
        for (int ks = 0; ks < 2; ++ks) {
            const int kb = ks * 8;
            uint32_t ah[4][4], al[4][4], bh[4][2], bl[4][2];
#pragma unroll
            for (int mi = 0; mi < 4; ++mi) {
                int o = aBase + mi * (16 * PITCH) + kb;
                ah[mi][0] = sAh[o];
                ah[mi][1] = sAh[o + 8 * PITCH];
                ah[mi][2] = sAh[o + 4];
                ah[mi][3] = sAh[o + 8 * PITCH + 4];
                al[mi][0] = sAl[o];
                al[mi][1] = sAl[o + 8 * PITCH];
                al[mi][2] = sAl[o + 4];
                al[mi][3] = sAl[o + 8 * PITCH + 4];
            }
#pragma unroll
            for (int ni = 0; ni < 4; ++ni) {
                int o = bBase + ni * (8 * PITCH) + kb;
                bh[ni][0] = sBh[o];
                bh[ni][1] = sBh[o + 4];
                bl[ni][0] = sBl[o];
                bl[ni][1] = sBl[o + 4];
            }
#pragma unroll
            for (int mi = 0; mi < 4; ++mi)
#pragma unroll
                for (int ni = 0; ni < 4; ++ni) {
                    mma_tf32(c[mi][ni], ah[mi], bh[ni]);
                    mma_tf32(c[mi][ni], al[mi], bh[ni]);
                    mma_tf32(c[mi][ni], ah[mi], bl[ni]);
                }
        }
        __syncthreads();
    }
#undef STAGE

#pragma unroll
    for (int mi = 0; mi < 4; ++mi) {
#pragma unroll
        for (int ni = 0; ni < 4; ++ni) {
            int r0 = mBase + warp_m * 64 + mi * 16 + (lane >> 2);
            int cc = nBase + warp_n * 32 + ni * 8 + 2 * (lane & 3);
            float2 v0 = make_float2(c[mi][ni][0], c[mi][ni][1]);
            float2 v1 = make_float2(c[mi][ni][2], c[mi][ni][3]);
            if (!QKV) {
                *(float2*)(C + (size_t)r0 * D_MODEL + cc) = v0;
                *(float2*)(C + (size_t)(r0 + 8) * D_MODEL + cc) = v1;
            } else {
                int h = cc >> 6, hd = cc & 63;
                int b0 = r0 / S, s0 = r0 - b0 * S;
                *(float2*)(C + (((size_t)b0 * N_HEADS + h) * S + s0) * HEAD_DIM + hd) = v0;
                int r1 = r0 + 8;
                int b1 = r1 / S, s1 = r1 - b1 * S;
                *(float2*)(C + (((size_t)b1 * N_HEADS + h) * S + s1) * HEAD_DIM + hd) = v1;
            }
        }
    }
}

// ---------------------------------------------------------------------------
// RoPE on Q and K in-place. Layout [BH, S, HD].
// ---------------------------------------------------------------------------
__global__ void rope_kernel(float* __restrict__ q, float* __restrict__ k,
                            int BH, int S) {
    int idx = blockIdx.x * blockDim.x + threadIdx.x;
    int total = BH * S * 32;
    if (idx >= total) return;
    int j = idx & 31;
    int s = (idx >> 5) % S;
    int bh = idx / (32 * S);

    float inv = powf(10000.0f, -(float)j / 32.0f);
    float ang = (float)s * inv;
    float sn, cs;
    sincosf(ang, &sn, &cs);

    size_t base = ((size_t)bh * S + s) * HEAD_DIM;
    float q1 = q[base + j], q2 = q[base + j + 32];
    q[base + j]      = q1 * cs - q2 * sn;
    q[base + j + 32] = q2 * cs + q1 * sn;
    float k1 = k[base + j], k2 = k[base + j + 32];
    k[base + j]      = k1 * cs - k2 * sn;
    k[base + j + 32] = k2 * cs + k1 * sn;
}

// ---------------------------------------------------------------------------
// Flash attention on tensor cores (tf32 split).
// 64 q-rows/CTA, 64-key tiles, 4 warps. QK^T: warp w owns score rows
// [16w,16w+16). PV computed as O^T = V^T * P^T so P's transposed smem store
// feeds B-fragments directly; warp w owns d-slice [16w,16w+16), accumulates
// O^T in registers across k-blocks. Writes tf32 hi/lo straight to g_xh/g_xl.
// Pitches: 72 = 8 mod 32 and 68 = 4 mod 32 chosen for conflict-free frag LDS.
// ---------------------------------------------------------------------------
#define FP 72
#define KP 68
#define OF_QH 0
#define OF_QL 4608
#define OF_K  9216
#define OF_V  13568
#define OF_PH 18176
#define OF_PL 22784
#define OF_AL 27392
#define OF_LI 27456
#define FL_SMEM ((27456 + 64) * 4)   // 110080 bytes

__global__ void __launch_bounds__(128, 2) flash_tc(const float* __restrict__ Q,
                                                   const float* __restrict__ K,
                                                   const float* __restrict__ V,
                                                   float* __restrict__ OH,
                                                   float* __restrict__ OL, int S) {
    extern __shared__ float sm[];
    float* Qh  = sm + OF_QH;
    float* Ql  = sm + OF_QL;
    float* Kf  = sm + OF_K;
    float* Vf  = sm + OF_V;
    float* Pth = sm + OF_PH;
    float* Ptl = sm + OF_PL;
    float* alph = sm + OF_AL;
    float* linv = sm + OF_LI;

    int tid = threadIdx.x;
    int lane = tid & 31;
    int w = tid >> 5;
    int g = lane >> 2;         // group id
    int t = lane & 3;          // thread-in-group

    int qb = blockIdx.x * 64;
    int bh = blockIdx.y;
    const float* Qg = Q + (size_t)bh * S * HEAD_DIM;
    const float* Kg = K + (size_t)bh * S * HEAD_DIM;
    const float* Vg = V + (size_t)bh * S * HEAD_DIM;

    uint32_t sK = stou(Kf), sV = stou(Vf);

    // Q: load, scale, split into smem (one-time)
#pragma unroll
    for (int i = 0; i < 32; ++i) {
        int e = i * 128 + tid;
        int r = e >> 6, d = e & 63;
        float q = Qg[(size_t)(qb + r) * HEAD_DIM + d] * 0.125f;
        float qh = tf32r(q);
        Qh[r * FP + d] = qh;
        Ql[r * FP + d] = q - qh;
    }

    float cO[8][4];
#pragma unroll
    for (int nt = 0; nt < 8; ++nt)
#pragma unroll
        for (int r = 0; r < 4; ++r) cO[nt][r] = 0.0f;

    float m0 = -1e30f, m1 = -1e30f, l0 = 0.0f, l1 = 0.0f;
    int qr0 = w * 16;          // score rows owned (QK phase)
    int dw = w * 16;           // d-slice owned (PV phase)

    int nkb = qb / 64 + 1;
    for (int kb = 0; kb < nkb; ++kb) {
        __syncthreads();       // prev PV done (and Q smem ready on kb=0)

        const float* kgb = Kg + (size_t)kb * 64 * HEAD_DIM;
        const float* vgb = Vg + (size_t)kb * 64 * HEAD_DIM;
#pragma unroll
        for (int i = 0; i < 8; ++i) {
            int ch = i * 128 + tid;
            int r = ch >> 4, c4 = ch & 15;
            cpasync16(sK + (uint32_t)(r * KP + c4 * 4) * 4u, kgb + r * 64 + c4 * 4);
        }
#pragma unroll
        for (int i = 0; i < 8; ++i) {
            int ch = i * 128 + tid;
            int r = ch >> 4, c4 = ch & 15;
            cpasync16(sV + (uint32_t)(r * FP + c4 * 4) * 4u, vgb + r * 64 + c4 * 4);
        }
        CP_COMMIT();
        CP_WAIT0();
        __syncthreads();

        // ---- S = Q K^T (split: Ah*Bh + Al*Bh + Ah*Bl) ----
        float cS[8][4];
#pragma unroll
        for (int nt = 0; nt < 8; ++nt)
#pragma unroll
            for (int r = 0; r < 4; ++r) cS[nt][r] = 0.0f;

#pragma unroll
        for (int ks = 0; ks < 8; ++ks) {
            int ao = (qr0 + g) * FP + ks * 8 + t;
            uint32_t ah[4], al[4];
            ah[0] = __float_as_uint(Qh[ao]);
            ah[1] = __float_as_uint(Qh[ao + 8 * FP]);
            ah[2] = __float_as_uint(Qh[ao + 4]);
            ah[3] = __float_as_uint(Qh[ao + 8 * FP + 4]);
            al[0] = __float_as_uint(Ql[ao]);
            al[1] = __float_as_uint(Ql[ao + 8 * FP]);
            al[2] = __float_as_uint(Ql[ao + 4]);
            al[3] = __float_as_uint(Ql[ao + 8 * FP + 4]);
#pragma unroll
            for (int nt = 0; nt < 8; ++nt) {
                int bo = (nt * 8 + g) * KP + ks * 8 + t;
                float k0 = Kf[bo], k1 = Kf[bo + 4];
                float kh0 = tf32r(k0), kh1 = tf32r(k1);
                uint32_t bhv[2] = {__float_as_uint(kh0), __float_as_uint(kh1)};
                uint32_t blv[2] = {__float_as_uint(k0 - kh0), __float_as_uint(k1 - kh1)};
                mma_tf32(cS[nt], ah, bhv);
                mma_tf32(cS[nt], al, bhv);
                mma_tf32(cS[nt], ah, blv);
            }
        }

        // ---- causal mask (diagonal block only) ----
        if (kb == nkb - 1) {
            int rg0 = qb + qr0 + g, rg1 = rg0 + 8;
#pragma unroll
            for (int nt = 0; nt < 8; ++nt) {
                int c0 = kb * 64 + nt * 8 + 2 * t;
                if (c0 > rg0) cS[nt][0] = -1e30f;
                if (c0 + 1 > rg0) cS[nt][1] = -1e30f;
                if (c0 > rg1) cS[nt][2] = -1e30f;
                if (c0 + 1 > rg1) cS[nt][3] = -1e30f;
            }
        }

        // ---- online softmax (rows qr0+g, qr0+g+8) ----
        float mx0 = -1e30f, mx1 = -1e30f;
#pragma unroll
        for (int nt = 0; nt < 8; ++nt) {
            mx0 = fmaxf(mx0, fmaxf(cS[nt][0], cS[nt][1]));
            mx1 = fmaxf(mx1, fmaxf(cS[nt][2], cS[nt][3]));
        }
        mx0 = fmaxf(mx0, __shfl_xor_sync(0xffffffffu, mx0, 1));
        mx0 = fmaxf(mx0, __shfl_xor_sync(0xffffffffu, mx0, 2));
        mx1 = fmaxf(mx1, __shfl_xor_sync(0xffffffffu, mx1, 1));
        mx1 = fmaxf(mx1, __shfl_xor_sync(0xffffffffu, mx1, 2));

        float mn0 = fmaxf(m0, mx0), mn1 = fmaxf(m1, mx1);
        float a0 = __expf(m0 - mn0), a1 = __expf(m1 - mn1);
        m0 = mn0; m1 = mn1;

        float s0 = 0.0f, s1 = 0.0f;
#pragma unroll
        for (int nt = 0; nt < 8; ++nt) {
#pragma unroll
            for (int e = 0; e < 2; ++e) {
                int j = nt * 8 + 2 * t + e;
                float p = __expf(cS[nt][e] - mn0);
                s0 += p;
                float ph = tf32r(p);
                Pth[j * FP + qr0 + g] = ph;
                Ptl[j * FP + qr0 + g] = p - ph;
                float p2 = __expf(cS[nt][2 + e] - mn1);
                s1 += p2;
                float p2h = tf32r(p2);
                Pth[j * FP + qr0 + g + 8] = p2h;
                Ptl[j * FP + qr0 + g + 8] = p2 - p2h;
            }
        }
        s0 += __shfl_xor_sync(0xffffffffu, s0, 1);
        s0 += __shfl_xor_sync(0xffffffffu, s0, 2);
        s1 += __shfl_xor_sync(0xffffffffu, s1, 1);
        s1 += __shfl_xor_sync(0xffffffffu, s1, 2);
        l0 = l0 * a0 + s0;
        l1 = l1 * a1 + s1;
        if (t == 0) {
            alph[qr0 + g] = a0;
            alph[qr0 + g + 8] = a1;
        }
        __syncthreads();

        // ---- O^T = O^T*diag(alpha) + V^T P^T ----
#pragma unroll
        for (int nt = 0; nt < 8; ++nt) {
            float af0 = alph[nt * 8 + 2 * t];
            float af1 = alph[nt * 8 + 2 * t + 1];
            cO[nt][0] *= af0; cO[nt][1] *= af1;
            cO[nt][2] *= af0; cO[nt][3] *= af1;
        }
#pragma unroll
        for (int ks = 0; ks < 8; ++ks) {
            int vo = (ks * 8 + t) * FP + dw + g;
            float v0 = Vf[vo], v1 = Vf[vo + 8];
            float v2 = Vf[vo + 4 * FP], v3 = Vf[vo + 4 * FP + 8];
            float vh0 = tf32r(v0), vh1 = tf32r(v1), vh2 = tf32r(v2), vh3 = tf32r(v3);
            uint32_t avh[4] = {__float_as_uint(vh0), __float_as_uint(vh1),
                               __float_as_uint(vh2), __float_as_uint(vh3)};
            uint32_t avl[4] = {__float_as_uint(v0 - vh0), __float_as_uint(v1 - vh1),
                               __float_as_uint(v2 - vh2), __float_as_uint(v3 - vh3)};
#pragma unroll
            for (int nt = 0; nt < 8; ++nt) {
                int po = (ks * 8 + t) * FP + nt * 8 + g;
                uint32_t bph[2] = {__float_as_uint(Pth[po]),
                                   __float_as_uint(Pth[po + 4 * FP])};
                uint32_t bpl[2] = {__float_as_uint(Ptl[po]),
                                   __float_as_uint(Ptl[po + 4 * FP])};
                mma_tf32(cO[nt], avh, bph);
                mma_tf32(cO[nt], avl, bph);
                mma_tf32(cO[nt], avh, bpl);
            }
        }
    }

    // ---- finalize ----
    if (t == 0) {
        linv[qr0 + g] = 1.0f / l0;
        linv[qr0 + g + 8] = 1.0f / l1;
    }
    __syncthreads();

    float* Ot = Pth;  // reuse as [i][68]
#pragma unroll
    for (int nt = 0; nt < 8; ++nt) {
        int i0 = nt * 8 + 2 * t;
        float li0 = linv[i0], li1 = linv[i0 + 1];
        Ot[i0 * 68 + dw + g] = cO[nt][0] * li0;
        Ot[(i0 + 1) * 68 + dw + g] = cO[nt][1] * li1;
        Ot[i0 * 68 + dw + g + 8] = cO[nt][2] * li0;
        Ot[(i0 + 1) * 68 + dw + g + 8] = cO[nt][3] * li1;
    }
    __syncthreads();

    // coalesced write, split hi/lo for the O-projection GEMM
    int b = bh >> 4, h = bh & 15;
    int i = tid >> 1, half = tid & 1;
    size_t obase = ((size_t)(b * S + qb + i)) * D_MODEL + h * HEAD_DIM + half * 32;
#pragma unroll
    for (int c4 = 0; c4 < 8; ++c4) {
        float4 o = *(float4*)&Ot[i * 68 + half * 32 + c4 * 4];
        float4 oh, ol;
        oh.x = tf32r(o.x); ol.x = o.x - oh.x;
        oh.y = tf32r(o.y); ol.y = o.y - oh.y;
        oh.z = tf32r(o.z); ol.z = o.z - oh.z;
        oh.w = tf32r(o.w); ol.w = o.w - oh.w;
        *(float4*)&OH[obase + c4 * 4] = oh;
        *(float4*)&OL[obase + c4 * 4] = ol;
    }
}

// ---------------- host side ----------------
extern "C" void kernel_launch(void* const* d_in, const int* in_sizes, int n_in,
                              void* d_out, int out_size) {
    const float* x  = (const float*)d_in[0];
    const float* Wq = (const float*)d_in[1];
    const float* Wk = (const float*)d_in[2];
    const float* Wv = (const float*)d_in[3];
    const float* Wo = (const float*)d_in[4];

    int B = in_sizes[0] / (SEQ * D_MODEL);
    if (B < 1) B = 1;
    if (B > MAXB) B = MAXB;
    int T = B * SEQ;
    int BH = B * N_HEADS;

    float *q, *k, *v, *xh, *xl, *wh, *wl;
    cudaGetSymbolAddress((void**)&q, g_q);
    cudaGetSymbolAddress((void**)&k, g_k);
    cudaGetSymbolAddress((void**)&v, g_v);
    cudaGetSymbolAddress((void**)&xh, g_xh);
    cudaGetSymbolAddress((void**)&xl, g_xl);
    cudaGetSymbolAddress((void**)&wh, g_wh);
    cudaGetSymbolAddress((void**)&wl, g_wl);

    const int GSMEM = 2 * BUFF * (int)sizeof(float);
    cudaFuncSetAttribute(tc_gemm<1>, cudaFuncAttributeMaxDynamicSharedMemorySize, GSMEM);
    cudaFuncSetAttribute(tc_gemm<0>, cudaFuncAttributeMaxDynamicSharedMemorySize, GSMEM);
    cudaFuncSetAttribute(flash_tc, cudaFuncAttributeMaxDynamicSharedMemorySize, FL_SMEM);

    const size_t WSZ = (size_t)D_MODEL * D_MODEL;

    // 1) split x and weights into tf32 hi/lo
    int n4 = T * D_MODEL / 4;
    split_kernel<<<(n4 + 255) / 256, 256>>>((const float4*)x, (float4*)xh, (float4*)xl, n4);
    splitw_kernel<<<dim3(256, 4), 256>>>(Wq, Wk, Wv, Wo, wh, wl);

    // 2) QKV projections on tensor cores
    tc_gemm<1><<<dim3(T / 128, D_MODEL / 128, 3), 256, GSMEM>>>(
        xh, xl, wh, wl, q, k, v, SEQ);

    // 3) RoPE
    int tot = BH * SEQ * 32;
    rope_kernel<<<(tot + 255) / 256, 256>>>(q, k, BH, SEQ);

    // 4) flash attention on tensor cores (writes split hi/lo directly)
    flash_tc<<<dim3(SEQ / 64, BH), 128, FL_SMEM>>>(q, k, v, xh, xl, SEQ);

    // 5) output projection on tensor cores
    tc_gemm<0><<<dim3(T / 128, D_MODEL / 128, 1), 256, GSMEM>>>(
        xh, xl, wh + 3 * WSZ, wl + 3 * WSZ, (float*)d_out, nullptr, nullptr, SEQ);
}

// round 11
// speedup vs baseline: 2.7185x; 1.7090x over previous
#include <cuda_runtime.h>
#include <cuda_bf16.h>
#include <math.h>
#include <stdint.h>

#define D_MODEL 1024
#define N_HEADS 16
#define HEAD_DIM 64
#define SEQ 2048
#define MAXB 2

typedef unsigned short ushort_t;

// ---------------- scratch (no allocations allowed) ----------------
__device__ __align__(1024) float g_q[MAXB * N_HEADS * SEQ * HEAD_DIM];
__device__ __align__(1024) float g_k[MAXB * N_HEADS * SEQ * HEAD_DIM];
__device__ __align__(1024) float g_v[MAXB * N_HEADS * SEQ * HEAD_DIM];
__device__ __align__(1024) ushort_t g_xh[MAXB * SEQ * D_MODEL];   // bf16 hi of x / attn-out
__device__ __align__(1024) ushort_t g_xl[MAXB * SEQ * D_MODEL];   // bf16 lo
__device__ __align__(1024) ushort_t g_wh[4 * D_MODEL * D_MODEL];  // bf16 hi of Wq,Wk,Wv,Wo
__device__ __align__(1024) ushort_t g_wl[4 * D_MODEL * D_MODEL];

// ---------------- helpers ----------------
__device__ __forceinline__ uint32_t stou(const void* p) {
    uint32_t a;
    asm("{ .reg .u64 t; cvta.to.shared.u64 t, %1; cvt.u32.u64 %0, t; }"
        : "=r"(a) : "l"(p));
    return a;
}
__device__ __forceinline__ uint32_t bfpack(float lo, float hi) {
    uint32_t r;
    asm("cvt.rn.bf16x2.f32 %0, %1, %2;" : "=r"(r) : "f"(hi), "f"(lo));
    return r;
}
__device__ __forceinline__ float bfr(float x) {   // round to bf16, back to float
    return __bfloat162float(__float2bfloat16_rn(x));
}
__device__ __forceinline__ void cpasync16(uint32_t dst, const void* src) {
    asm volatile("cp.async.cg.shared.global [%0], [%1], 16;"
                 :: "r"(dst), "l"(src) : "memory");
}
#define CP_COMMIT() asm volatile("cp.async.commit_group;" ::: "memory")
#define CP_WAIT1()  asm volatile("cp.async.wait_group 1;" ::: "memory")
#define CP_WAIT0()  asm volatile("cp.async.wait_group 0;" ::: "memory")

__device__ __forceinline__ void ldx4(uint32_t r[4], uint32_t addr) {
    asm volatile("ldmatrix.sync.aligned.m8n8.x4.shared.b16 {%0,%1,%2,%3}, [%4];"
                 : "=r"(r[0]), "=r"(r[1]), "=r"(r[2]), "=r"(r[3]) : "r"(addr));
}
__device__ __forceinline__ void ldx4t(uint32_t r[4], uint32_t addr) {
    asm volatile("ldmatrix.sync.aligned.m8n8.x4.trans.shared.b16 {%0,%1,%2,%3}, [%4];"
                 : "=r"(r[0]), "=r"(r[1]), "=r"(r[2]), "=r"(r[3]) : "r"(addr));
}
__device__ __forceinline__ void mma_bf(float c[4], const uint32_t a[4],
                                       uint32_t b0, uint32_t b1) {
    asm volatile(
        "mma.sync.aligned.m16n8k16.row.col.f32.bf16.bf16.f32 "
        "{%0,%1,%2,%3}, {%4,%5,%6,%7}, {%8,%9}, {%0,%1,%2,%3};"
        : "+f"(c[0]), "+f"(c[1]), "+f"(c[2]), "+f"(c[3])
        : "r"(a[0]), "r"(a[1]), "r"(a[2]), "r"(a[3]), "r"(b0), "r"(b1));
}

// ---------------- split kernels (fp32 -> bf16 hi + bf16 lo) ----------------
__global__ void split_kernel(const float4* __restrict__ src, uint2* __restrict__ hi,
                             uint2* __restrict__ lo, int n4) {
    int i = blockIdx.x * 256 + threadIdx.x;
    if (i >= n4) return;
    float4 v = src[i];
    float hx = bfr(v.x), hy = bfr(v.y), hz = bfr(v.z), hw = bfr(v.w);
    uint2 h, l;
    h.x = bfpack(hx, hy); h.y = bfpack(hz, hw);
    l.x = bfpack(v.x - hx, v.y - hy); l.y = bfpack(v.z - hz, v.w - hw);
    hi[i] = h; lo[i] = l;
}

__global__ void splitw_kernel(const float* __restrict__ w0, const float* __restrict__ w1,
                              const float* __restrict__ w2, const float* __restrict__ w3,
                              ushort_t* __restrict__ hi, ushort_t* __restrict__ lo) {
    int y = blockIdx.y;
    const float* w = (y == 0) ? w0 : (y == 1) ? w1 : (y == 2) ? w2 : w3;
    const int n4 = (D_MODEL * D_MODEL) / 4;
    const float4* s4 = (const float4*)w;
    uint2* h4 = (uint2*)(hi + (size_t)y * D_MODEL * D_MODEL);
    uint2* l4 = (uint2*)(lo + (size_t)y * D_MODEL * D_MODEL);
    for (int i = blockIdx.x * 256 + threadIdx.x; i < n4; i += gridDim.x * 256) {
        float4 v = s4[i];
        float hx = bfr(v.x), hy = bfr(v.y), hz = bfr(v.z), hw = bfr(v.w);
        uint2 h, l;
        h.x = bfpack(hx, hy); h.y = bfpack(hz, hw);
        l.x = bfpack(v.x - hx, v.y - hy); l.y = bfpack(v.z - hz, v.w - hw);
        h4[i] = h; l4[i] = l;
    }
}

// ---------------------------------------------------------------------------
// bf16 split GEMM: D = Ah*Bh^T + Al*Bh^T + Ah*Bl^T via m16n8k16 + ldmatrix.
// C = A(TxK) * W^T, W [N,K] row-major. Tile 128x128, BK=32, 8 warps (2x4),
// warp tile 64x32. cp.async double-buffered.
// ---------------------------------------------------------------------------
#define GP 80                 // bytes per 32-bf16 row (64 + 16 pad)
#define OPB (128 * GP)        // bytes per operand tile = 10240
#define STAGEB (4 * OPB)      // 40960
#define NCH (D_MODEL / 32)    // 32 chunks

template <int QKV>
__global__ void __launch_bounds__(256, 1) tc_gemm(
    const ushort_t* __restrict__ Ah, const ushort_t* __restrict__ Al,
    const ushort_t* __restrict__ Wh, const ushort_t* __restrict__ Wl,
    float* __restrict__ C0, float* __restrict__ C1, float* __restrict__ C2,
    int S) {
    extern __shared__ char smc[];
    uint32_t sb = stou(smc);

    int tid = threadIdx.x;
    int lane = tid & 31;
    int wid = tid >> 5;
    int warp_m = wid >> 2;
    int warp_n = wid & 3;

    int mBase = blockIdx.x * 128;
    int nBase = blockIdx.y * 128;

    const ushort_t* Bh = Wh;
    const ushort_t* Bl = Wl;
    float* C = C0;
    if (QKV) {
        size_t woff = (size_t)blockIdx.z * D_MODEL * D_MODEL;
        Bh = Wh + woff; Bl = Wl + woff;
        if (blockIdx.z == 1) C = C1;
        else if (blockIdx.z == 2) C = C2;
    }

    // staging: thread -> row r (0..63, +64), 16B seg sg (0..3)
    int r = tid >> 2, sg = tid & 3;
    const ushort_t* pAh = Ah + (size_t)(mBase + r) * D_MODEL + sg * 8;
    const ushort_t* pAl = Al + (size_t)(mBase + r) * D_MODEL + sg * 8;
    const ushort_t* pBh = Bh + (size_t)(nBase + r) * D_MODEL + sg * 8;
    const ushort_t* pBl = Bl + (size_t)(nBase + r) * D_MODEL + sg * 8;
    uint32_t dst0 = (uint32_t)(r * GP + sg * 16);
    const uint32_t rStep = 64 * GP;
    const size_t gStep = (size_t)64 * D_MODEL;

#define STAGE(buf, k0)                                                        \
    do {                                                                      \
        uint32_t s0 = sb + (uint32_t)(buf) * STAGEB + dst0;                   \
        cpasync16(s0,                  pAh + (k0));                           \
        cpasync16(s0 + rStep,          pAh + (k0) + gStep);                   \
        cpasync16(s0 + OPB,            pAl + (k0));                           \
        cpasync16(s0 + OPB + rStep,    pAl + (k0) + gStep);                   \
        cpasync16(s0 + 2 * OPB,        pBh + (k0));                           \
        cpasync16(s0 + 2 * OPB + rStep,pBh + (k0) + gStep);                   \
        cpasync16(s0 + 3 * OPB,        pBl + (k0));                          \
        cpasync16(s0 + 3 * OPB + rStep,pBl + (k0) + gStep);                   \
    } while (0)

    float c[4][4][4];
#pragma unroll
    for (int mi = 0; mi < 4; ++mi)
#pragma unroll
        for (int ni = 0; ni < 4; ++ni)
#pragma unroll
            for (int q = 0; q < 4; ++q) c[mi][ni][q] = 0.0f;

    uint32_t aOff = (uint32_t)((warp_m * 64 + (lane & 15)) * GP + (lane >> 4) * 16);
    uint32_t bOff = (uint32_t)((warp_n * 32 + (lane & 15)) * GP + (lane >> 4) * 16);

    STAGE(0, 0);
    CP_COMMIT();

    for (int ch = 0; ch < NCH; ++ch) {
        if (ch + 1 < NCH) {
            STAGE((ch + 1) & 1, (ch + 1) * 32);
            CP_COMMIT();
            CP_WAIT1();
        } else {
            CP_WAIT0();
        }
        __syncthreads();

        uint32_t stg = sb + (uint32_t)(ch & 1) * STAGEB;
#pragma unroll
        for (int ks = 0; ks < 2; ++ks) {
            uint32_t ah[4][4], al[4][4], bh4[2][4], bl4[2][4];
#pragma unroll
            for (int mi = 0; mi < 4; ++mi) {
                uint32_t a = stg + aOff + (uint32_t)(mi * 16 * GP + ks * 32);
                ldx4(ah[mi], a);
                ldx4(al[mi], a + OPB);
            }
#pragma unroll
            for (int np = 0; np < 2; ++np) {
                uint32_t a = stg + 2 * OPB + bOff + (uint32_t)(np * 16 * GP + ks * 32);
                ldx4(bh4[np], a);
                ldx4(bl4[np], a + OPB);
            }
#pragma unroll
            for (int mi = 0; mi < 4; ++mi)
#pragma unroll
                for (int np = 0; np < 2; ++np) {
                    mma_bf(c[mi][2 * np], ah[mi], bh4[np][0], bh4[np][2]);
                    mma_bf(c[mi][2 * np], al[mi], bh4[np][0], bh4[np][2]);
                    mma_bf(c[mi][2 * np], ah[mi], bl4[np][0], bl4[np][2]);
                    mma_bf(c[mi][2 * np + 1], ah[mi], bh4[np][1], bh4[np][3]);
                    mma_bf(c[mi][2 * np + 1], al[mi], bh4[np][1], bh4[np][3]);
                    mma_bf(c[mi][2 * np + 1], ah[mi], bl4[np][1], bl4[np][3]);
                }
        }
        __syncthreads();
    }
#undef STAGE

    int g = lane >> 2, t = lane & 3;
#pragma unroll
    for (int mi = 0; mi < 4; ++mi) {
#pragma unroll
        for (int ni = 0; ni < 4; ++ni) {
            int r0 = mBase + warp_m * 64 + mi * 16 + g;
            int cc = nBase + warp_n * 32 + ni * 8 + 2 * t;
            float2 v0 = make_float2(c[mi][ni][0], c[mi][ni][1]);
            float2 v1 = make_float2(c[mi][ni][2], c[mi][ni][3]);
            if (!QKV) {
                *(float2*)(C + (size_t)r0 * D_MODEL + cc) = v0;
                *(float2*)(C + (size_t)(r0 + 8) * D_MODEL + cc) = v1;
            } else {
                int h = cc >> 6, hd = cc & 63;
                int b0 = r0 / S, s0 = r0 - b0 * S;
                *(float2*)(C + (((size_t)b0 * N_HEADS + h) * S + s0) * HEAD_DIM + hd) = v0;
                int r1 = r0 + 8;
                int b1 = r1 / S, s1 = r1 - b1 * S;
                *(float2*)(C + (((size_t)b1 * N_HEADS + h) * S + s1) * HEAD_DIM + hd) = v1;
            }
        }
    }
}

// ---------------------------------------------------------------------------
// RoPE on Q and K in-place. Layout [BH, S, HD].
// ---------------------------------------------------------------------------
__global__ void rope_kernel(float* __restrict__ q, float* __restrict__ k,
                            int BH, int S) {
    int idx = blockIdx.x * blockDim.x + threadIdx.x;
    int total = BH * S * 32;
    if (idx >= total) return;
    int j = idx & 31;
    int s = (idx >> 5) % S;
    int bh = idx / (32 * S);

    float inv = powf(10000.0f, -(float)j / 32.0f);
    float ang = (float)s * inv;
    float sn, cs;
    sincosf(ang, &sn, &cs);

    size_t base = ((size_t)bh * S + s) * HEAD_DIM;
    float q1 = q[base + j], q2 = q[base + j + 32];
    q[base + j]      = q1 * cs - q2 * sn;
    q[base + j + 32] = q2 * cs + q1 * sn;
    float k1 = k[base + j], k2 = k[base + j + 32];
    k[base + j]      = k1 * cs - k2 * sn;
    k[base + j + 32] = k2 * cs + k1 * sn;
}

// ---------------------------------------------------------------------------
// Flash attention, split-bf16 mma + ldmatrix. 64 q/CTA, 64-key tiles, 4 warps.
// Warp w owns score rows AND O rows [16w,16w+16): P never leaves registers.
// Q fragments hoisted out of the kb loop. K/V: cp.async fp32 staging
// (prefetched) -> one split pass -> bf16 smem tiles (pitch 144B, ldmatrix-
// conflict-free). Writes bf16 hi/lo O directly for the Wo GEMM.
// ---------------------------------------------------------------------------
#define FPB 144               // bytes per 64-bf16 row (128 + 16 pad)
#define FQH 0
#define FQL 9216
#define FKH 18432
#define FKL 27648
#define FVH 36864
#define FVL 46080
#define FKF 55296             // fp32 K staging [64][64]
#define FVF 71680             // fp32 V staging
#define FL_SMEM 88064

__global__ void __launch_bounds__(128, 2) flash_bf(const float* __restrict__ Q,
                                                   const float* __restrict__ K,
                                                   const float* __restrict__ V,
                                                   ushort_t* __restrict__ OH,
                                                   ushort_t* __restrict__ OL, int S) {
    extern __shared__ char smc[];
    uint32_t sb = stou(smc);
    float* KF = (float*)(smc + FKF);
    float* VF = (float*)(smc + FVF);

    int tid = threadIdx.x;
    int lane = tid & 31;
    int w = tid >> 5;
    int g = lane >> 2, t = lane & 3;

    int qb = blockIdx.x * 64;
    int bh = blockIdx.y;
    const float* Qg = Q + (size_t)bh * S * HEAD_DIM;
    const float* Kg = K + (size_t)bh * S * HEAD_DIM;
    const float* Vg = V + (size_t)bh * S * HEAD_DIM;

    int nkb = qb / 64 + 1;

    // stage K/V tile kb into fp32 staging via cp.async
#define STAGE_KV(kb)                                                          \
    do {                                                                      \
        const float* kg_ = Kg + (size_t)(kb) * 64 * HEAD_DIM;                 \
        const float* vg_ = Vg + (size_t)(kb) * 64 * HEAD_DIM;                 \
        _Pragma("unroll")                                                     \
        for (int it = 0; it < 8; ++it) {                                      \
            int e = it * 128 + tid;                                           \
            int rr = e >> 4, c4 = e & 15;                                     \
            cpasync16(sb + FKF + (uint32_t)(rr * 256 + c4 * 16),              \
                      kg_ + rr * 64 + c4 * 4);                                \
            cpasync16(sb + FVF + (uint32_t)(rr * 256 + c4 * 16),              \
                      vg_ + rr * 64 + c4 * 4);                                \
        }                                                                     \
        CP_COMMIT();                                                          \
    } while (0)

    STAGE_KV(0);

    // Q: load, scale, split to bf16 smem (one-time)
#pragma unroll
    for (int it = 0; it < 8; ++it) {
        int e = it * 128 + tid;
        int rr = e >> 4, c4 = e & 15;
        float4 v = *(const float4*)(Qg + (size_t)(qb + rr) * HEAD_DIM + c4 * 4);
        v.x *= 0.125f; v.y *= 0.125f; v.z *= 0.125f; v.w *= 0.125f;
        float hx = bfr(v.x), hy = bfr(v.y), hz = bfr(v.z), hw = bfr(v.w);
        uint2 h = make_uint2(bfpack(hx, hy), bfpack(hz, hw));
        uint2 l = make_uint2(bfpack(v.x - hx, v.y - hy), bfpack(v.z - hz, v.w - hw));
        *(uint2*)(smc + FQH + rr * FPB + c4 * 8) = h;
        *(uint2*)(smc + FQL + rr * FPB + c4 * 8) = l;
    }
    __syncthreads();

    // hoist Q fragments (rows w*16..w*16+15, all 64 d) into registers
    uint32_t qh[4][4], ql[4][4];
    {
        uint32_t a0 = sb + FQH + (uint32_t)((w * 16 + (lane & 15)) * FPB + (lane >> 4) * 16);
#pragma unroll
        for (int ks = 0; ks < 4; ++ks) {
            ldx4(qh[ks], a0 + ks * 32);
            ldx4(ql[ks], a0 + ks * 32 + (FQL - FQH));
        }
    }

    float cO[8][4];
#pragma unroll
    for (int nt = 0; nt < 8; ++nt)
#pragma unroll
        for (int q = 0; q < 4; ++q) cO[nt][q] = 0.0f;
    float m0 = -1e30f, m1 = -1e30f, l0 = 0.0f, l1 = 0.0f;

    for (int kb = 0; kb < nkb; ++kb) {
        CP_WAIT0();
        __syncthreads();   // staging ready; prev-iter mma reads of bf16 tiles done

        // split K/V fp32 staging -> bf16 tiles
#pragma unroll
        for (int it = 0; it < 8; ++it) {
            int e = it * 128 + tid;
            int rr = e >> 4, c4 = e & 15;
            float4 kv = *(float4*)(KF + rr * 64 + c4 * 4);
            float hx = bfr(kv.x), hy = bfr(kv.y), hz = bfr(kv.z), hw = bfr(kv.w);
            *(uint2*)(smc + FKH + rr * FPB + c4 * 8) =
                make_uint2(bfpack(hx, hy), bfpack(hz, hw));
            *(uint2*)(smc + FKL + rr * FPB + c4 * 8) =
                make_uint2(bfpack(kv.x - hx, kv.y - hy), bfpack(kv.z - hz, kv.w - hw));
            float4 vv = *(float4*)(VF + rr * 64 + c4 * 4);
            float ux = bfr(vv.x), uy = bfr(vv.y), uz = bfr(vv.z), uw = bfr(vv.w);
            *(uint2*)(smc + FVH + rr * FPB + c4 * 8) =
                make_uint2(bfpack(ux, uy), bfpack(uz, uw));
            *(uint2*)(smc + FVL + rr * FPB + c4 * 8) =
                make_uint2(bfpack(vv.x - ux, vv.y - uy), bfpack(vv.z - uz, vv.w - uw));
        }
        __syncthreads();

        if (kb + 1 < nkb) STAGE_KV(kb + 1);   // prefetch overlaps compute

        // ---- S = Q K^T ----
        float cS[8][4];
#pragma unroll
        for (int nt = 0; nt < 8; ++nt)
#pragma unroll
            for (int q = 0; q < 4; ++q) cS[nt][q] = 0.0f;

        uint32_t kBase = sb + FKH + (uint32_t)((lane & 15) * FPB + (lane >> 4) * 16);
#pragma unroll
        for (int ks = 0; ks < 4; ++ks) {
#pragma unroll
            for (int np = 0; np < 4; ++np) {
                uint32_t a = kBase + (uint32_t)(np * 16 * FPB + ks * 32);
                uint32_t bh4[4], bl4[4];
                ldx4(bh4, a);
                ldx4(bl4, a + (FKL - FKH));
                mma_bf(cS[2 * np], qh[ks], bh4[0], bh4[2]);
                mma_bf(cS[2 * np], ql[ks], bh4[0], bh4[2]);
                mma_bf(cS[2 * np], qh[ks], bl4[0], bl4[2]);
                mma_bf(cS[2 * np + 1], qh[ks], bh4[1], bh4[3]);
                mma_bf(cS[2 * np + 1], ql[ks], bh4[1], bh4[3]);
                mma_bf(cS[2 * np + 1], qh[ks], bl4[1], bl4[3]);
            }
        }

        // ---- causal mask (diagonal block only) ----
        if (kb == nkb - 1) {
            int rg0 = qb + w * 16 + g, rg1 = rg0 + 8;
#pragma unroll
            for (int nt = 0; nt < 8; ++nt) {
                int c0 = kb * 64 + nt * 8 + 2 * t;
                if (c0 > rg0) cS[nt][0] = -1e30f;
                if (c0 + 1 > rg0) cS[nt][1] = -1e30f;
                if (c0 > rg1) cS[nt][2] = -1e30f;
                if (c0 + 1 > rg1) cS[nt][3] = -1e30f;
            }
        }

        // ---- online softmax; pack P into bf16 A-fragments (registers only) ----
        float mx0 = -1e30f, mx1 = -1e30f;
#pragma unroll
        for (int nt = 0; nt < 8; ++nt) {
            mx0 = fmaxf(mx0, fmaxf(cS[nt][0], cS[nt][1]));
            mx1 = fmaxf(mx1, fmaxf(cS[nt][2], cS[nt][3]));
        }
        mx0 = fmaxf(mx0, __shfl_xor_sync(0xffffffffu, mx0, 1));
        mx0 = fmaxf(mx0, __shfl_xor_sync(0xffffffffu, mx0, 2));
        mx1 = fmaxf(mx1, __shfl_xor_sync(0xffffffffu, mx1, 1));
        mx1 = fmaxf(mx1, __shfl_xor_sync(0xffffffffu, mx1, 2));

        float mn0 = fmaxf(m0, mx0), mn1 = fmaxf(m1, mx1);
        float a0 = __expf(m0 - mn0), a1 = __expf(m1 - mn1);
        m0 = mn0; m1 = mn1;

        uint32_t ph[4][4], pl[4][4];
        float s0 = 0.0f, s1 = 0.0f;
#pragma unroll
        for (int nt = 0; nt < 8; ++nt) {
            float p0 = __expf(cS[nt][0] - mn0);
            float p1 = __expf(cS[nt][1] - mn0);
            float p2 = __expf(cS[nt][2] - mn1);
            float p3 = __expf(cS[nt][3] - mn1);
            s0 += p0 + p1;
            s1 += p2 + p3;
            float h0 = bfr(p0), h1 = bfr(p1), h2 = bfr(p2), h3 = bfr(p3);
            int ks = nt >> 1;
            int o = (nt & 1) * 2;   // 0 -> a0/a1 slots, 1 -> a2/a3 slots
            ph[ks][o] = bfpack(h0, h1);
            ph[ks][o + 1] = bfpack(h2, h3);
            pl[ks][o] = bfpack(p0 - h0, p1 - h1);
            pl[ks][o + 1] = bfpack(p2 - h2, p3 - h3);
        }
        s0 += __shfl_xor_sync(0xffffffffu, s0, 1);
        s0 += __shfl_xor_sync(0xffffffffu, s0, 2);
        s1 += __shfl_xor_sync(0xffffffffu, s1, 1);
        s1 += __shfl_xor_sync(0xffffffffu, s1, 2);
        l0 = l0 * a0 + s0;
        l1 = l1 * a1 + s1;

        // ---- O = O*alpha + P V ----
#pragma unroll
        for (int nt = 0; nt < 8; ++nt) {
            cO[nt][0] *= a0; cO[nt][1] *= a0;
            cO[nt][2] *= a1; cO[nt][3] *= a1;
        }
        uint32_t vBase = sb + FVH + (uint32_t)((lane & 15) * FPB + (lane >> 4) * 16);
#pragma unroll
        for (int ks = 0; ks < 4; ++ks) {
#pragma unroll
            for (int np = 0; np < 4; ++np) {
                uint32_t a = vBase + (uint32_t)(ks * 16 * FPB + np * 32);
                uint32_t vh4[4], vl4[4];
                ldx4t(vh4, a);
                ldx4t(vl4, a + (FVL - FVH));
                mma_bf(cO[2 * np], ph[ks], vh4[0], vh4[1]);
                mma_bf(cO[2 * np], pl[ks], vh4[0], vh4[1]);
                mma_bf(cO[2 * np], ph[ks], vl4[0], vl4[1]);
                mma_bf(cO[2 * np + 1], ph[ks], vh4[2], vh4[3]);
                mma_bf(cO[2 * np + 1], pl[ks], vh4[2], vh4[3]);
                mma_bf(cO[2 * np + 1], ph[ks], vl4[2], vl4[3]);
            }
        }
    }
#undef STAGE_KV

    // ---- finalize: scale by 1/l, split to bf16 hi/lo, write for Wo GEMM ----
    float li0 = 1.0f / l0, li1 = 1.0f / l1;
    int b = bh >> 4, h = bh & 15;
    int row0 = qb + w * 16 + g;
    size_t base0 = ((size_t)(b * S + row0)) * D_MODEL + h * HEAD_DIM;
    size_t base1 = base0 + (size_t)8 * D_MODEL;
#pragma unroll
    for (int nt = 0; nt < 8; ++nt) {
        int d = nt * 8 + 2 * t;
        float o00 = cO[nt][0] * li0, o01 = cO[nt][1] * li0;
        float o10 = cO[nt][2] * li1, o11 = cO[nt][3] * li1;
        float h00 = bfr(o00), h01 = bfr(o01), h10 = bfr(o10), h11 = bfr(o11);
        *(uint32_t*)(OH + base0 + d) = bfpack(h00, h01);
        *(uint32_t*)(OL + base0 + d) = bfpack(o00 - h00, o01 - h01);
        *(uint32_t*)(OH + base1 + d) = bfpack(h10, h11);
        *(uint32_t*)(OL + base1 + d) = bfpack(o10 - h10, o11 - h11);
    }
}

// ---------------- host side ----------------
extern "C" void kernel_launch(void* const* d_in, const int* in_sizes, int n_in,
                              void* d_out, int out_size) {
    const float* x  = (const float*)d_in[0];
    const float* Wq = (const float*)d_in[1];
    const float* Wk = (const float*)d_in[2];
    const float* Wv = (const float*)d_in[3];
    const float* Wo = (const float*)d_in[4];

    int B = in_sizes[0] / (SEQ * D_MODEL);
    if (B < 1) B = 1;
    if (B > MAXB) B = MAXB;
    int T = B * SEQ;
    int BH = B * N_HEADS;

    float *q, *k, *v;
    ushort_t *xh, *xl, *wh, *wl;
    cudaGetSymbolAddress((void**)&q, g_q);
    cudaGetSymbolAddress((void**)&k, g_k);
    cudaGetSymbolAddress((void**)&v, g_v);
    cudaGetSymbolAddress((void**)&xh, g_xh);
    cudaGetSymbolAddress((void**)&xl, g_xl);
    cudaGetSymbolAddress((void**)&wh, g_wh);
    cudaGetSymbolAddress((void**)&wl, g_wl);

    const int GSMEM = 2 * STAGEB;   // 81920
    cudaFuncSetAttribute(tc_gemm<1>, cudaFuncAttributeMaxDynamicSharedMemorySize, GSMEM);
    cudaFuncSetAttribute(tc_gemm<0>, cudaFuncAttributeMaxDynamicSharedMemorySize, GSMEM);
    cudaFuncSetAttribute(flash_bf, cudaFuncAttributeMaxDynamicSharedMemorySize, FL_SMEM);

    const size_t WSZ = (size_t)D_MODEL * D_MODEL;

    // 1) split x and weights into bf16 hi/lo
    int n4 = T * D_MODEL / 4;
    split_kernel<<<(n4 + 255) / 256, 256>>>((const float4*)x, (uint2*)xh, (uint2*)xl, n4);
    splitw_kernel<<<dim3(256, 4), 256>>>(Wq, Wk, Wv, Wo, wh, wl);

    // 2) QKV projections (bf16 split tensor cores)
    tc_gemm<1><<<dim3(T / 128, D_MODEL / 128, 3), 256, GSMEM>>>(
        xh, xl, wh, wl, q, k, v, SEQ);

    // 3) RoPE
    int tot = BH * SEQ * 32;
    rope_kernel<<<(tot + 255) / 256, 256>>>(q, k, BH, SEQ);

    // 4) flash attention (bf16 split tensor cores; writes split hi/lo)
    flash_bf<<<dim3(SEQ / 64, BH), 128, FL_SMEM>>>(q, k, v, xh, xl, SEQ);

    // 5) output projection
    tc_gemm<0><<<dim3(T / 128, D_MODEL / 128, 1), 256, GSMEM>>>(
        xh, xl, wh + 3 * WSZ, wl + 3 * WSZ, (float*)d_out, nullptr, nullptr, SEQ);
}